// round 15
// baseline (speedup 1.0000x reference)
#include <cuda_runtime.h>
#include <cuda_bf16.h>
#include <math.h>
#include <stdint.h>

#define B_   2
#define S_   2048
#define D_   512
#define L_   4
#define H_   8
#define DH   64
#define M_   (B_*S_)      // 4096 rows
#define DI   512          // H*DH
#define QKVN 1536
#define DHID 1365
#define FFN  2730         // 2*DHID
#define KPX  256          // k-pairs for K=512
#define KPY  688          // k-pairs (padded) for K=1365

// ---------------- scratch (no allocation allowed) ----------------
__device__ float    g_t   [M_ * D_];            // residual stream
__device__ float    g_fv  [M_ * DI];            // first layer's v (fp32)
__device__ float    g_mix [M_ * H_];            // sigmoid gates
__device__ float2   g_rt  [S_ * 32];            // rope cos/sin table
__device__ uint32_t g_xh  [M_ * KPX], g_xl [M_ * KPX];   // rmsnorm out (split)
__device__ uint32_t g_oh  [M_ * KPX], g_ol [M_ * KPX];   // attn out (split)
__device__ uint32_t g_yh  [M_ * KPY], g_yl [M_ * KPY];   // gelu out (split; padding stays 0)
__device__ uint32_t g_qh2 [M_ * KPX], g_ql2 [M_ * KPX];  // roped+scaled q (split)
__device__ uint32_t g_kh2 [M_ * KPX], g_kl2 [M_ * KPX];  // roped k (split)
__device__ uint32_t g_vh2 [M_ * KPX], g_vl2 [M_ * KPX];  // mixed v (split)
// converted weights (transposed [N][Kp], hi/lo planes)
__device__ uint32_t g_wqh [L_ * QKVN * KPX], g_wql [L_ * QKVN * KPX];
__device__ uint32_t g_woh [L_ * DI   * KPX], g_wol [L_ * DI   * KPX];
__device__ uint32_t g_wfh [L_ * FFN  * KPX], g_wfl [L_ * FFN  * KPX];
__device__ uint32_t g_wgh [L_ * DI   * KPY], g_wgl [L_ * DI   * KPY];

// ---------------- helpers ----------------
__device__ __forceinline__ uint32_t smem_u32(const void* p) {
    uint32_t a;
    asm("{ .reg .u64 t; cvta.to.shared.u64 t, %1; cvt.u32.u64 %0, t; }" : "=r"(a) : "l"(p));
    return a;
}
__device__ __forceinline__ uint32_t pack_bf(float x, float y) {
    uint32_t r;
    asm("cvt.rn.bf16x2.f32 %0, %1, %2;" : "=r"(r) : "f"(y), "f"(x));
    return r;
}
__device__ __forceinline__ void split2(float x, float y, uint32_t& hi, uint32_t& lo) {
    hi = pack_bf(x, y);
    float rx = x - __uint_as_float(hi << 16);
    float ry = y - __uint_as_float(hi & 0xFFFF0000u);
    lo = pack_bf(rx, ry);
}
__device__ __forceinline__ void mma16816(float* c, const uint32_t* a, const uint32_t* b) {
    asm volatile(
        "mma.sync.aligned.m16n8k16.row.col.f32.bf16.bf16.f32 "
        "{%0,%1,%2,%3}, {%4,%5,%6,%7}, {%8,%9}, {%0,%1,%2,%3};"
        : "+f"(c[0]), "+f"(c[1]), "+f"(c[2]), "+f"(c[3])
        : "r"(a[0]), "r"(a[1]), "r"(a[2]), "r"(a[3]), "r"(b[0]), "r"(b[1]));
}
__device__ __forceinline__ void ldsm4(uint32_t& r0, uint32_t& r1, uint32_t& r2, uint32_t& r3,
                                      uint32_t addr) {
    asm volatile("ldmatrix.sync.aligned.m8n8.x4.shared.b16 {%0,%1,%2,%3}, [%4];"
                 : "=r"(r0), "=r"(r1), "=r"(r2), "=r"(r3) : "r"(addr));
}
__device__ __forceinline__ void ldsm4t(uint32_t& r0, uint32_t& r1, uint32_t& r2, uint32_t& r3,
                                       uint32_t addr) {
    asm volatile("ldmatrix.sync.aligned.m8n8.x4.trans.shared.b16 {%0,%1,%2,%3}, [%4];"
                 : "=r"(r0), "=r"(r1), "=r"(r2), "=r"(r3) : "r"(addr));
}
__device__ __forceinline__ void cp16(uint32_t dst, const void* src, int sz) {
    asm volatile("cp.async.ca.shared.global [%0], [%1], 16, %2;"
                 :: "r"(dst), "l"(src), "r"(sz) : "memory");
}

// ---------------- weight convert: W[K][N] fp32 -> Wh/Wl [N][Kps]; z = layer --------
__global__ void wconv_k(const float* __restrict__ W0, uint32_t* __restrict__ Wh0,
                        uint32_t* __restrict__ Wl0, int K, int N, int Kps, int ilv,
                        size_t wstride, size_t pstride) {
    const float* W = W0 + blockIdx.z * wstride;
    uint32_t* Wh = Wh0 + blockIdx.z * pstride;
    uint32_t* Wl = Wl0 + blockIdx.z * pstride;
    __shared__ float2 tile[32][33];
    int kp0 = blockIdx.x * 32, n0 = blockIdx.y * 32;
    int tx = threadIdx.x, ty = threadIdx.y;   // 32 x 8
    #pragma unroll
    for (int j = 0; j < 4; j++) {
        int kp = kp0 + ty + j * 8, k = 2 * kp, n = n0 + tx;
        int on = n;
        if (ilv) on = (n & 1) ? (n >> 1) + DHID : (n >> 1);
        float a = 0.0f, b = 0.0f;
        if (n < N) {
            if (k < K)     a = W[(size_t)k * N + on];
            if (k + 1 < K) b = W[(size_t)(k + 1) * N + on];
        }
        tile[ty + j * 8][tx] = make_float2(a, b);
    }
    __syncthreads();
    #pragma unroll
    for (int j = 0; j < 4; j++) {
        int n = n0 + ty + j * 8, kp = kp0 + tx;
        if (n < N && kp < Kps) {
            float2 v = tile[tx][ty + j * 8];
            uint32_t hi, lo;
            split2(v.x, v.y, hi, lo);
            Wh[(size_t)n * Kps + kp] = hi;
            Wl[(size_t)n * Kps + kp] = lo;
        }
    }
}

// ---------------- rope table ----------------
__global__ void ropetab_k(float2* __restrict__ rt) {
    int idx = blockIdx.x * 256 + threadIdx.x;
    if (idx >= S_ * 32) return;
    int pair = idx & 31, pos = idx >> 5;
    float inv = expf(-logf(10000.0f) * (float)pair * (1.0f / 32.0f));
    float s, c;
    sincosf((float)pos * inv, &s, &c);
    rt[idx] = make_float2(c, s);
}

// ================= split-bf16 HMMA GEMM, double-buffered cp.async + ldmatrix ======
// template MT = m-tiles per warp (4 -> BM=128, 2 -> BM=64). BN=128.
#define BPL 2560
template<int MT>
__global__ void __launch_bounds__(256, 2) gemm_bs(
    int N, int Kp, int ldap, int ldbp, int ldc,
    const uint32_t* __restrict__ Agh, const uint32_t* __restrict__ Agl,
    const uint32_t* __restrict__ Bgh, const uint32_t* __restrict__ Bgl,
    float* __restrict__ C, const float* __restrict__ bias,
    const float* __restrict__ addsrc, int mode,
    uint32_t* __restrict__ Yh, uint32_t* __restrict__ Yl,
    const float2* __restrict__ rt, const float* __restrict__ mixp,
    float* __restrict__ fvp,
    uint32_t* __restrict__ Qh, uint32_t* __restrict__ Ql,
    uint32_t* __restrict__ Kh2, uint32_t* __restrict__ Kl2,
    uint32_t* __restrict__ Vh2, uint32_t* __restrict__ Vl2, int layer0)
{
    constexpr int BM  = MT * 32;
    constexpr int APL = BM * 20;           // u32 per A plane
    constexpr int STG = 2 * APL + 2 * BPL; // u32 per stage
    extern __shared__ uint32_t sm[];
    int tid = threadIdx.x;
    int wid = tid >> 5, lane = tid & 31;
    int m0 = blockIdx.y * BM, n0 = blockIdx.x * 128;
    int wm = (wid >> 2) * (MT * 16), wn = (wid & 3) * 32;
    int g = lane >> 2, t = lane & 3;

    float acc[MT][4][4];
    #pragma unroll
    for (int i = 0; i < MT; i++)
        #pragma unroll
        for (int j = 0; j < 4; j++)
            #pragma unroll
            for (int q = 0; q < 4; q++) acc[i][j][q] = 0.0f;

    uint32_t smb = smem_u32(sm);
    int nch = Kp >> 4;

    auto load_chunk = [&](int c, int buf) {
        int kp0 = c << 4;
        uint32_t base = smb + (uint32_t)buf * (STG * 4);
        #pragma unroll
        for (int i = 0; i < 2; i++) {
            int e = i * 256 + tid;
            int row = e >> 2, seg = (e & 3) * 4;
            uint32_t soff = (uint32_t)(row * 20 + seg) * 4;
            if (row < BM) {
                size_t aoff = (size_t)(m0 + row) * ldap + kp0 + seg;
                cp16(base + soff, Agh + aoff, 16);
                cp16(base + APL * 4 + soff, Agl + aoff, 16);
            }
            int nn = n0 + row;
            int sz = (nn < N) ? 16 : 0;
            size_t boff = (size_t)(nn < N ? nn : 0) * ldbp + kp0 + seg;
            cp16(base + 2 * APL * 4 + soff, Bgh + boff, sz);
            cp16(base + (2 * APL + BPL) * 4 + soff, Bgl + boff, sz);
        }
        asm volatile("cp.async.commit_group;" ::: "memory");
    };

    int a_row = lane & 15, a_colo = (lane >> 4) * 4;
    int b_l8 = lane & 7, b_seg = lane >> 3;

    load_chunk(0, 0);
    for (int c = 0; c < nch; c++) {
        if (c + 1 < nch) {
            load_chunk(c + 1, (c + 1) & 1);
            asm volatile("cp.async.wait_group 1;" ::: "memory");
        } else {
            asm volatile("cp.async.wait_group 0;" ::: "memory");
        }
        __syncthreads();

        uint32_t abh = smb + (uint32_t)(c & 1) * (STG * 4);
        uint32_t abl = abh + APL * 4;
        uint32_t bbh = abh + 2 * APL * 4;
        uint32_t bbl = bbh + BPL * 4;

        #pragma unroll
        for (int s = 0; s < 2; s++) {
            uint32_t afh[MT][4], afl[MT][4];
            #pragma unroll
            for (int mt = 0; mt < MT; mt++) {
                uint32_t off = (uint32_t)(((wm + mt * 16 + a_row) * 20 + s * 8 + a_colo) * 4);
                ldsm4(afh[mt][0], afh[mt][1], afh[mt][2], afh[mt][3], abh + off);
                ldsm4(afl[mt][0], afl[mt][1], afl[mt][2], afl[mt][3], abl + off);
            }
            uint32_t bfh[4][2], bfl[4][2];
            #pragma unroll
            for (int np = 0; np < 2; np++) {
                int brow = wn + (np * 2 + (b_seg >> 1)) * 8 + b_l8;
                int bcol = s * 8 + (b_seg & 1) * 4;
                uint32_t off = (uint32_t)((brow * 20 + bcol) * 4);
                ldsm4(bfh[np*2][0], bfh[np*2][1], bfh[np*2+1][0], bfh[np*2+1][1], bbh + off);
                ldsm4(bfl[np*2][0], bfl[np*2][1], bfl[np*2+1][0], bfl[np*2+1][1], bbl + off);
            }
            #pragma unroll
            for (int mt = 0; mt < MT; mt++)
                #pragma unroll
                for (int nt = 0; nt < 4; nt++) {
                    mma16816(acc[mt][nt], afh[mt], bfh[nt]);
                    mma16816(acc[mt][nt], afh[mt], bfl[nt]);
                    mma16816(acc[mt][nt], afl[mt], bfh[nt]);
                }
        }
        __syncthreads();
    }

    if (mode == 0) {
        #pragma unroll
        for (int mt = 0; mt < MT; mt++) {
            int r0 = m0 + wm + mt * 16 + g;
            #pragma unroll
            for (int nt = 0; nt < 4; nt++) {
                int col = n0 + wn + nt * 8 + 2 * t;
                #pragma unroll
                for (int half = 0; half < 2; half++) {
                    int row = r0 + half * 8;
                    float v0 = acc[mt][nt][half * 2 + 0];
                    float v1 = acc[mt][nt][half * 2 + 1];
                    if (col < N) {
                        if (bias)   v0 += bias[col];
                        if (addsrc) v0 += addsrc[(size_t)row * ldc + col];
                        C[(size_t)row * ldc + col] = v0;
                    }
                    if (col + 1 < N) {
                        if (bias)   v1 += bias[col + 1];
                        if (addsrc) v1 += addsrc[(size_t)row * ldc + col + 1];
                        C[(size_t)row * ldc + col + 1] = v1;
                    }
                }
            }
        }
    } else if (mode == 1) {
        #pragma unroll
        for (int mt = 0; mt < MT; mt++) {
            int r0 = m0 + wm + mt * 16 + g;
            #pragma unroll
            for (int nt = 0; nt < 4; nt++) {
                int col = n0 + wn + nt * 8 + 2 * t;
                int j = col >> 1;
                bool valid = col < N;
                #pragma unroll
                for (int half = 0; half < 2; half++) {
                    int row = r0 + half * 8;
                    float y = 0.0f;
                    if (valid) {
                        float a  = acc[mt][nt][half * 2 + 0] + bias[j];
                        float gg = acc[mt][nt][half * 2 + 1] + bias[j + DHID];
                        y = a * 0.5f * gg * (1.0f + erff(gg * 0.70710678118654752f));
                    }
                    float y1 = __shfl_down_sync(0xffffffffu, y, 1);
                    if ((t & 1) == 0) {
                        int kp = j >> 1;
                        if (kp < KPY) {
                            uint32_t hi, lo;
                            split2(y, y1, hi, lo);
                            Yh[(size_t)row * KPY + kp] = hi;
                            Yl[(size_t)row * KPY + kp] = lo;
                        }
                    }
                }
            }
        }
    } else {
        int region = n0 >> 9;   // 0=q, 1=k, 2=v
        #pragma unroll
        for (int mt = 0; mt < MT; mt++) {
            int r0 = m0 + wm + mt * 16 + g;
            #pragma unroll
            for (int nt = 0; nt < 4; nt++) {
                int col = n0 + wn + nt * 8 + 2 * t;
                int cc = col & 511;
                #pragma unroll
                for (int half = 0; half < 2; half++) {
                    int row = r0 + half * 8;
                    float v0 = acc[mt][nt][half * 2 + 0];
                    float v1 = acc[mt][nt][half * 2 + 1];
                    size_t idx = (size_t)row * KPX + (cc >> 1);
                    if (region <= 1) {
                        float2 cs = rt[(row & (S_ - 1)) * 32 + ((cc & 63) >> 1)];
                        float r1 = v0 * cs.x - v1 * cs.y;
                        float r2 = v0 * cs.y + v1 * cs.x;
                        if (region == 0) { r1 *= 0.125f; r2 *= 0.125f; }
                        uint32_t hi, lo;
                        split2(r1, r2, hi, lo);
                        if (region == 0) { Qh[idx] = hi; Ql[idx] = lo; }
                        else             { Kh2[idx] = hi; Kl2[idx] = lo; }
                    } else {
                        if (layer0) {
                            fvp[(size_t)row * DI + cc] = v0;
                            fvp[(size_t)row * DI + cc + 1] = v1;
                        } else {
                            float mx = mixp[(size_t)row * H_ + (cc >> 6)];
                            float f0 = fvp[(size_t)row * DI + cc];
                            float f1 = fvp[(size_t)row * DI + cc + 1];
                            v0 += mx * (f0 - v0);
                            v1 += mx * (f1 - v1);
                        }
                        uint32_t hi, lo;
                        split2(v0, v1, hi, lo);
                        Vh2[idx] = hi; Vl2[idx] = lo;
                    }
                }
            }
        }
    }
}

// ================= flash attention: Br=128, double-buffered cp.async tiles ========
#define ATSM_PL  2304    // uint32 per plane (64*36)
#define ATSM_BUF 9216    // uint32 per buffer (4 planes)
__global__ void __launch_bounds__(256) attn_mma(
    const uint32_t* __restrict__ Qh, const uint32_t* __restrict__ Ql,
    const uint32_t* __restrict__ Kg_h, const uint32_t* __restrict__ Kg_l,
    const uint32_t* __restrict__ Vg_h, const uint32_t* __restrict__ Vg_l,
    uint32_t* __restrict__ Oh, uint32_t* __restrict__ Ol)
{
    extern __shared__ uint32_t asmem[];
    int Qb = blockIdx.x;                 // 128-row query tile
    int h  = blockIdx.y & 7, b = blockIdx.y >> 3;
    int tid = threadIdx.x, w = tid >> 5, lane = tid & 31;
    int g = lane >> 2, t = lane & 3;
    int row0 = b * S_ + Qb * 128;

    uint32_t base = smem_u32(asmem);
    int l8 = lane & 7, seg8 = lane >> 3;

    auto load_tile = [&](int J, int buf) {
        int kr = b * S_ + J * 64;
        uint32_t bb = base + (uint32_t)buf * (ATSM_BUF * 4);
        #pragma unroll
        for (int i = 0; i < 2; i++) {
            int cc = i * 256 + tid;          // 0..511
            int row = cc >> 3, sg = cc & 7;
            size_t src = (size_t)(kr + row) * KPX + h * 32 + sg * 4;
            uint32_t soff = (uint32_t)(row * 36 + sg * 4) * 4;
            cp16(bb + soff, Kg_h + src, 16);
            cp16(bb + ATSM_PL * 4 + soff, Kg_l + src, 16);
            cp16(bb + ATSM_PL * 8 + soff, Vg_h + src, 16);
            cp16(bb + ATSM_PL * 12 + soff, Vg_l + src, 16);
        }
        asm volatile("cp.async.commit_group;" ::: "memory");
    };

    uint32_t qh[4][4], ql[4][4];
    #pragma unroll
    for (int kt = 0; kt < 4; kt++) {
        #pragma unroll
        for (int q = 0; q < 4; q++) {
            int rr = row0 + w * 16 + g + ((q & 1) ? 8 : 0);
            int kp = kt * 8 + t + ((q & 2) ? 4 : 0);
            size_t idx = (size_t)rr * KPX + h * 32 + kp;
            qh[kt][q] = Qh[idx];
            ql[kt][q] = Ql[idx];
        }
    }

    float Oa[8][4];
    #pragma unroll
    for (int i = 0; i < 8; i++)
        #pragma unroll
        for (int q = 0; q < 4; q++) Oa[i][q] = 0.0f;
    float m_[2] = {-INFINITY, -INFINITY};
    float l_[2] = {0.0f, 0.0f};

    int Jmax = 2 * Qb + 1;
    load_tile(0, 0);
    for (int J = 0; J <= Jmax; J++) {
        if (J < Jmax) {
            load_tile(J + 1, (J + 1) & 1);
            asm volatile("cp.async.wait_group 1;" ::: "memory");
        } else {
            asm volatile("cp.async.wait_group 0;" ::: "memory");
        }
        __syncthreads();

        uint32_t kbh = base + (uint32_t)(J & 1) * (ATSM_BUF * 4);
        uint32_t kbl = kbh + ATSM_PL * 4;
        uint32_t vbh = kbh + ATSM_PL * 8;
        uint32_t vbl = kbh + ATSM_PL * 12;

        int ntS = 8;
        if (J == 2 * Qb)       { if (w < 2) ntS = 4; }
        else if (J == Jmax)    { ntS = (w < 4) ? 0 : ((w < 6) ? 4 : 8); }

        if (ntS > 0) {
            int ktPV = ntS >> 1;

            float Sa[8][4];
            for (int nt = 0; nt < ntS; nt++) {
                Sa[nt][0] = Sa[nt][1] = Sa[nt][2] = Sa[nt][3] = 0.0f;
                uint32_t kfh[4][2], kfl[4][2];
                uint32_t off0 = (uint32_t)(((8 * nt + l8) * 36 + seg8 * 4) * 4);
                ldsm4(kfh[0][0], kfh[0][1], kfh[1][0], kfh[1][1], kbh + off0);
                ldsm4(kfh[2][0], kfh[2][1], kfh[3][0], kfh[3][1], kbh + off0 + 64);
                ldsm4(kfl[0][0], kfl[0][1], kfl[1][0], kfl[1][1], kbl + off0);
                ldsm4(kfl[2][0], kfl[2][1], kfl[3][0], kfl[3][1], kbl + off0 + 64);
                #pragma unroll
                for (int kt = 0; kt < 4; kt++) {
                    mma16816(Sa[nt], qh[kt], kfh[kt]);
                    mma16816(Sa[nt], qh[kt], kfl[kt]);
                    mma16816(Sa[nt], ql[kt], kfh[kt]);
                }
            }

            float alpha[2];
            #pragma unroll
            for (int half = 0; half < 2; half++) {
                float mx = -INFINITY;
                for (int nt = 0; nt < ntS; nt++) {
                    mx = fmaxf(mx, Sa[nt][half * 2]);
                    mx = fmaxf(mx, Sa[nt][half * 2 + 1]);
                }
                mx = fmaxf(mx, __shfl_xor_sync(0xffffffffu, mx, 1));
                mx = fmaxf(mx, __shfl_xor_sync(0xffffffffu, mx, 2));
                float mn = fmaxf(m_[half], mx);
                alpha[half] = __expf(m_[half] - mn);
                m_[half] = mn;
                float ps = 0.0f;
                for (int nt = 0; nt < ntS; nt++) {
                    float p0 = __expf(Sa[nt][half * 2]     - mn);
                    float p1 = __expf(Sa[nt][half * 2 + 1] - mn);
                    Sa[nt][half * 2]     = p0;
                    Sa[nt][half * 2 + 1] = p1;
                    ps += p0 + p1;
                }
                l_[half] = l_[half] * alpha[half] + ps;
            }
            #pragma unroll
            for (int nt = 0; nt < 8; nt++) {
                Oa[nt][0] *= alpha[0]; Oa[nt][1] *= alpha[0];
                Oa[nt][2] *= alpha[1]; Oa[nt][3] *= alpha[1];
            }

            uint32_t ph[4][4], pl[4][4];
            for (int kt = 0; kt < ktPV; kt++) {
                split2(Sa[2 * kt][0],     Sa[2 * kt][1],     ph[kt][0], pl[kt][0]);
                split2(Sa[2 * kt][2],     Sa[2 * kt][3],     ph[kt][1], pl[kt][1]);
                split2(Sa[2 * kt + 1][0], Sa[2 * kt + 1][1], ph[kt][2], pl[kt][2]);
                split2(Sa[2 * kt + 1][2], Sa[2 * kt + 1][3], ph[kt][3], pl[kt][3]);
            }

            int npair = ktPV >> 1;
            for (int p = 0; p < npair; p++) {
                int key = 32 * p + seg8 * 8 + l8;
                #pragma unroll
                for (int nt = 0; nt < 8; nt++) {
                    uint32_t off = (uint32_t)((key * 36 + nt * 4) * 4);
                    uint32_t bh0, bh1, bh2, bh3, bl0, bl1, bl2, bl3;
                    ldsm4t(bh0, bh1, bh2, bh3, vbh + off);
                    ldsm4t(bl0, bl1, bl2, bl3, vbl + off);
                    uint32_t b0h[2] = {bh0, bh1}, b0l[2] = {bl0, bl1};
                    uint32_t b1h[2] = {bh2, bh3}, b1l[2] = {bl2, bl3};
                    mma16816(Oa[nt], ph[2*p],     b0h);
                    mma16816(Oa[nt], ph[2*p],     b0l);
                    mma16816(Oa[nt], pl[2*p],     b0h);
                    mma16816(Oa[nt], ph[2*p + 1], b1h);
                    mma16816(Oa[nt], ph[2*p + 1], b1l);
                    mma16816(Oa[nt], pl[2*p + 1], b1h);
                }
            }
        }
        __syncthreads();
    }

    float linv[2];
    #pragma unroll
    for (int half = 0; half < 2; half++) {
        float l = l_[half];
        l += __shfl_xor_sync(0xffffffffu, l, 1);
        l += __shfl_xor_sync(0xffffffffu, l, 2);
        linv[half] = 1.0f / l;
    }
    int r0 = w * 16 + g, r1 = r0 + 8;
    #pragma unroll
    for (int nt = 0; nt < 8; nt++) {
        int kp = h * 32 + 4 * nt + t;
        uint32_t hi, lo;
        split2(Oa[nt][0] * linv[0], Oa[nt][1] * linv[0], hi, lo);
        Oh[(size_t)(row0 + r0) * KPX + kp] = hi;
        Ol[(size_t)(row0 + r0) * KPX + kp] = lo;
        split2(Oa[nt][2] * linv[1], Oa[nt][3] * linv[1], hi, lo);
        Oh[(size_t)(row0 + r1) * KPX + kp] = hi;
        Ol[(size_t)(row0 + r1) * KPX + kp] = lo;
    }
}

// ---------------- rmsnorm -> split output ----------------
__global__ void rmsnorm_split_k(const float* __restrict__ in, const float* __restrict__ w,
                                uint32_t* __restrict__ Xh, uint32_t* __restrict__ Xl) {
    int row = blockIdx.x;
    const float4* ip = (const float4*)(in + (size_t)row * D_);
    float4 v = ip[threadIdx.x];
    float ss = v.x*v.x + v.y*v.y + v.z*v.z + v.w*v.w;
    #pragma unroll
    for (int o = 16; o; o >>= 1) ss += __shfl_xor_sync(0xffffffffu, ss, o);
    __shared__ float sred[4];
    if ((threadIdx.x & 31) == 0) sred[threadIdx.x >> 5] = ss;
    __syncthreads();
    float tot = sred[0] + sred[1] + sred[2] + sred[3];
    float sc = rsqrtf(tot * (1.0f / 512.0f) + 1.1920929e-7f);
    const float4* wp = (const float4*)w;
    float4 wv = wp[threadIdx.x];
    float o0 = v.x * sc * wv.x, o1 = v.y * sc * wv.y;
    float o2 = v.z * sc * wv.z, o3 = v.w * sc * wv.w;
    uint32_t h0, l0, h1, l1;
    split2(o0, o1, h0, l0);
    split2(o2, o3, h1, l1);
    size_t base = (size_t)row * KPX + threadIdx.x * 2;
    Xh[base] = h0; Xh[base + 1] = h1;
    Xl[base] = l0; Xl[base + 1] = l1;
}

// ---------------- mix gate ----------------
__global__ void mix_k(const uint32_t* __restrict__ Xh, const uint32_t* __restrict__ Xl,
                      const float* __restrict__ mw, const float* __restrict__ mb,
                      float* __restrict__ mix) {
    int row = blockIdx.x;
    int lane = threadIdx.x & 31;
    int h = threadIdx.x >> 5;
    float dot = 0.0f;
    #pragma unroll
    for (int kp = lane; kp < KPX; kp += 32) {
        uint32_t hv = Xh[(size_t)row * KPX + kp], lv = Xl[(size_t)row * KPX + kp];
        float x0 = __uint_as_float(hv << 16) + __uint_as_float(lv << 16);
        float x1 = __uint_as_float(hv & 0xFFFF0000u) + __uint_as_float(lv & 0xFFFF0000u);
        dot += x0 * mw[(2 * kp) * H_ + h] + x1 * mw[(2 * kp + 1) * H_ + h];
    }
    #pragma unroll
    for (int o = 16; o; o >>= 1) dot += __shfl_xor_sync(0xffffffffu, dot, o);
    if (lane == 0)
        mix[(size_t)row * H_ + h] = 1.0f / (1.0f + expf(-(dot + mb[h])));
}

// ---------------- rmsnorm fp32 out (final) ----------------
__global__ void rmsnorm_k(const float* __restrict__ in, const float* __restrict__ w,
                          float* __restrict__ out) {
    int row = blockIdx.x;
    const float4* ip = (const float4*)(in + (size_t)row * D_);
    float4 v = ip[threadIdx.x];
    float ss = v.x*v.x + v.y*v.y + v.z*v.z + v.w*v.w;
    #pragma unroll
    for (int o = 16; o; o >>= 1) ss += __shfl_xor_sync(0xffffffffu, ss, o);
    __shared__ float sred[4];
    if ((threadIdx.x & 31) == 0) sred[threadIdx.x >> 5] = ss;
    __syncthreads();
    float tot = sred[0] + sred[1] + sred[2] + sred[3];
    float sc = rsqrtf(tot * (1.0f / 512.0f) + 1.1920929e-7f);
    const float4* wp = (const float4*)w;
    float4 wv = wp[threadIdx.x];
    float4 o4;
    o4.x = v.x * sc * wv.x; o4.y = v.y * sc * wv.y;
    o4.z = v.z * sc * wv.z; o4.w = v.w * sc * wv.w;
    ((float4*)(out + (size_t)row * D_))[threadIdx.x] = o4;
}

// ---------------- launch ----------------
extern "C" void kernel_launch(void* const* d_in, const int* in_sizes, int n_in,
                              void* d_out, int out_size) {
    const float* tokens       = (const float*)d_in[0];
    const float* attn_norm_w  = (const float*)d_in[1];
    const float* qkv_w        = (const float*)d_in[2];
    const float* out_w        = (const float*)d_in[3];
    const float* mix_w        = (const float*)d_in[4];
    const float* mix_b        = (const float*)d_in[5];
    const float* ff_norm_w    = (const float*)d_in[6];
    const float* ff_in_w      = (const float*)d_in[7];
    const float* ff_in_b      = (const float*)d_in[8];
    const float* ff_out_w     = (const float*)d_in[9];
    const float* ff_out_b     = (const float*)d_in[10];
    const float* final_norm_w = (const float*)d_in[11];

    float *t_, *fv_, *mix_;
    float2* rt_;
    uint32_t *xh_, *xl_, *oh_, *ol_, *yh_, *yl_;
    uint32_t *qh2_, *ql2_, *kh2_, *kl2_, *vh2_, *vl2_;
    uint32_t *wqh_, *wql_, *woh_, *wol_, *wfh_, *wfl_, *wgh_, *wgl_;
    cudaGetSymbolAddress((void**)&t_,   g_t);
    cudaGetSymbolAddress((void**)&fv_,  g_fv);
    cudaGetSymbolAddress((void**)&mix_, g_mix);
    cudaGetSymbolAddress((void**)&rt_,  g_rt);
    cudaGetSymbolAddress((void**)&xh_,  g_xh);
    cudaGetSymbolAddress((void**)&xl_,  g_xl);
    cudaGetSymbolAddress((void**)&oh_,  g_oh);
    cudaGetSymbolAddress((void**)&ol_,  g_ol);
    cudaGetSymbolAddress((void**)&yh_,  g_yh);
    cudaGetSymbolAddress((void**)&yl_,  g_yl);
    cudaGetSymbolAddress((void**)&qh2_, g_qh2);
    cudaGetSymbolAddress((void**)&ql2_, g_ql2);
    cudaGetSymbolAddress((void**)&kh2_, g_kh2);
    cudaGetSymbolAddress((void**)&kl2_, g_kl2);
    cudaGetSymbolAddress((void**)&vh2_, g_vh2);
    cudaGetSymbolAddress((void**)&vl2_, g_vl2);
    cudaGetSymbolAddress((void**)&wqh_, g_wqh);
    cudaGetSymbolAddress((void**)&wql_, g_wql);
    cudaGetSymbolAddress((void**)&woh_, g_woh);
    cudaGetSymbolAddress((void**)&wol_, g_wol);
    cudaGetSymbolAddress((void**)&wfh_, g_wfh);
    cudaGetSymbolAddress((void**)&wfl_, g_wfl);
    cudaGetSymbolAddress((void**)&wgh_, g_wgh);
    cudaGetSymbolAddress((void**)&wgl_, g_wgl);

    const int GSM2 = 2 * (2 * 64 * 20 + 2 * BPL) * 4;    // 61440
    const int ASM  = 2 * ATSM_BUF * 4;
    static int smem_set = 0;
    if (!smem_set) {
        cudaFuncSetAttribute(gemm_bs<2>, cudaFuncAttributeMaxDynamicSharedMemorySize, GSM2);
        cudaFuncSetAttribute(attn_mma, cudaFuncAttributeMaxDynamicSharedMemorySize, ASM);
        smem_set = 1;
    }

    ropetab_k<<<(S_ * 32 + 255) / 256, 256>>>(rt_);

    dim3 cb(32, 8);
    wconv_k<<<dim3(KPX / 32, QKVN / 32, L_), cb>>>(
        qkv_w, wqh_, wql_, D_, QKVN, KPX, 0,
        (size_t)D_ * QKVN, (size_t)QKVN * KPX);
    wconv_k<<<dim3(KPX / 32, DI / 32, L_), cb>>>(
        out_w, woh_, wol_, DI, D_, KPX, 0,
        (size_t)DI * D_, (size_t)DI * KPX);
    wconv_k<<<dim3(KPX / 32, (FFN + 31) / 32, L_), cb>>>(
        ff_in_w, wfh_, wfl_, D_, FFN, KPX, 1,
        (size_t)D_ * FFN, (size_t)FFN * KPX);
    wconv_k<<<dim3((KPY + 31) / 32, DI / 32, L_), cb>>>(
        ff_out_w, wgh_, wgl_, DHID, D_, KPY, 0,
        (size_t)DHID * D_, (size_t)DI * KPY);

    for (int l = 0; l < L_; l++) {
        const float* res_in = (l == 0) ? tokens : t_;

        rmsnorm_split_k<<<M_, 128>>>(res_in, attn_norm_w + l * D_, xh_, xl_);

        if (l > 0)
            mix_k<<<M_, 256>>>(xh_, xl_, mix_w + (size_t)l * D_ * H_, mix_b + l * H_, mix_);

        gemm_bs<2><<<dim3(QKVN / 128, M_ / 64), 256, GSM2>>>(
            QKVN, KPX, KPX, KPX, 0,
            xh_, xl_, wqh_ + (size_t)l * QKVN * KPX, wql_ + (size_t)l * QKVN * KPX,
            nullptr, nullptr, nullptr, 2, nullptr, nullptr,
            rt_, mix_, fv_, qh2_, ql2_, kh2_, kl2_, vh2_, vl2_, (l == 0) ? 1 : 0);

        attn_mma<<<dim3(S_ / 128, B_ * H_), 256, ASM>>>(
            qh2_, ql2_, kh2_, kl2_, vh2_, vl2_, oh_, ol_);

        gemm_bs<2><<<dim3(D_ / 128, M_ / 64), 256, GSM2>>>(
            D_, KPX, KPX, KPX, D_,
            oh_, ol_, woh_ + (size_t)l * DI * KPX, wol_ + (size_t)l * DI * KPX,
            t_, nullptr, res_in, 0, nullptr, nullptr,
            nullptr, nullptr, nullptr, nullptr, nullptr, nullptr, nullptr, nullptr, nullptr, 0);

        rmsnorm_split_k<<<M_, 128>>>(t_, ff_norm_w + l * D_, xh_, xl_);

        gemm_bs<2><<<dim3((FFN + 127) / 128, M_ / 64), 256, GSM2>>>(
            FFN, KPX, KPX, KPX, 0,
            xh_, xl_, wfh_ + (size_t)l * FFN * KPX, wfl_ + (size_t)l * FFN * KPX,
            nullptr, ff_in_b + (size_t)l * FFN, nullptr, 1, yh_, yl_,
            nullptr, nullptr, nullptr, nullptr, nullptr, nullptr, nullptr, nullptr, nullptr, 0);

        gemm_bs<2><<<dim3(D_ / 128, M_ / 64), 256, GSM2>>>(
            D_, KPY, KPY, KPY, D_,
            yh_, yl_, wgh_ + (size_t)l * DI * KPY, wgl_ + (size_t)l * DI * KPY,
            t_, ff_out_b + (size_t)l * D_, t_, 0, nullptr, nullptr,
            nullptr, nullptr, nullptr, nullptr, nullptr, nullptr, nullptr, nullptr, nullptr, 0);
    }

    rmsnorm_k<<<M_, 128>>>(t_, final_norm_w, (float*)d_out);
}

// round 16
// speedup vs baseline: 1.0672x; 1.0672x over previous
#include <cuda_runtime.h>
#include <cuda_bf16.h>
#include <math.h>
#include <stdint.h>

#define B_   2
#define S_   2048
#define D_   512
#define L_   4
#define H_   8
#define DH   64
#define M_   (B_*S_)      // 4096 rows
#define DI   512          // H*DH
#define QKVN 1536
#define DHID 1365
#define FFN  2730         // 2*DHID
#define KPX  256          // k-pairs for K=512
#define KPY  688          // k-pairs (padded) for K=1365

// ---------------- scratch (no allocation allowed) ----------------
__device__ float    g_t   [M_ * D_];            // residual stream
__device__ float    g_fv  [M_ * DI];            // first layer's v (fp32)
__device__ float    g_mix [M_ * H_];            // sigmoid gates
__device__ float2   g_rt  [S_ * 32];            // rope cos/sin table
__device__ uint32_t g_xh  [M_ * KPX], g_xl [M_ * KPX];   // rmsnorm out (split)
__device__ uint32_t g_oh  [M_ * KPX], g_ol [M_ * KPX];   // attn out (split)
__device__ uint32_t g_yh  [M_ * KPY], g_yl [M_ * KPY];   // gelu out (split; padding stays 0)
__device__ uint32_t g_qh2 [M_ * KPX], g_ql2 [M_ * KPX];  // roped+scaled q (split)
__device__ uint32_t g_kh2 [M_ * KPX], g_kl2 [M_ * KPX];  // roped k (split)
__device__ uint32_t g_vh2 [M_ * KPX], g_vl2 [M_ * KPX];  // mixed v (split)
// converted weights (transposed [N][Kp], hi/lo planes)
__device__ uint32_t g_wqh [L_ * QKVN * KPX], g_wql [L_ * QKVN * KPX];
__device__ uint32_t g_woh [L_ * DI   * KPX], g_wol [L_ * DI   * KPX];
__device__ uint32_t g_wfh [L_ * FFN  * KPX], g_wfl [L_ * FFN  * KPX];
__device__ uint32_t g_wgh [L_ * DI   * KPY], g_wgl [L_ * DI   * KPY];

// ---------------- helpers ----------------
__device__ __forceinline__ uint32_t smem_u32(const void* p) {
    uint32_t a;
    asm("{ .reg .u64 t; cvta.to.shared.u64 t, %1; cvt.u32.u64 %0, t; }" : "=r"(a) : "l"(p));
    return a;
}
__device__ __forceinline__ uint32_t pack_bf(float x, float y) {
    uint32_t r;
    asm("cvt.rn.bf16x2.f32 %0, %1, %2;" : "=r"(r) : "f"(y), "f"(x));
    return r;
}
__device__ __forceinline__ void split2(float x, float y, uint32_t& hi, uint32_t& lo) {
    hi = pack_bf(x, y);
    float rx = x - __uint_as_float(hi << 16);
    float ry = y - __uint_as_float(hi & 0xFFFF0000u);
    lo = pack_bf(rx, ry);
}
__device__ __forceinline__ void mma16816(float* c, const uint32_t* a, const uint32_t* b) {
    asm volatile(
        "mma.sync.aligned.m16n8k16.row.col.f32.bf16.bf16.f32 "
        "{%0,%1,%2,%3}, {%4,%5,%6,%7}, {%8,%9}, {%0,%1,%2,%3};"
        : "+f"(c[0]), "+f"(c[1]), "+f"(c[2]), "+f"(c[3])
        : "r"(a[0]), "r"(a[1]), "r"(a[2]), "r"(a[3]), "r"(b[0]), "r"(b[1]));
}
__device__ __forceinline__ void ldsm4(uint32_t& r0, uint32_t& r1, uint32_t& r2, uint32_t& r3,
                                      uint32_t addr) {
    asm volatile("ldmatrix.sync.aligned.m8n8.x4.shared.b16 {%0,%1,%2,%3}, [%4];"
                 : "=r"(r0), "=r"(r1), "=r"(r2), "=r"(r3) : "r"(addr));
}
__device__ __forceinline__ void ldsm4t(uint32_t& r0, uint32_t& r1, uint32_t& r2, uint32_t& r3,
                                       uint32_t addr) {
    asm volatile("ldmatrix.sync.aligned.m8n8.x4.trans.shared.b16 {%0,%1,%2,%3}, [%4];"
                 : "=r"(r0), "=r"(r1), "=r"(r2), "=r"(r3) : "r"(addr));
}
__device__ __forceinline__ void cp16(uint32_t dst, const void* src, int sz) {
    asm volatile("cp.async.ca.shared.global [%0], [%1], 16, %2;"
                 :: "r"(dst), "l"(src), "r"(sz) : "memory");
}

// ---------------- weight convert: W[K][N] fp32 -> Wh/Wl [N][Kps]; z = layer --------
__global__ void wconv_k(const float* __restrict__ W0, uint32_t* __restrict__ Wh0,
                        uint32_t* __restrict__ Wl0, int K, int N, int Kps, int ilv,
                        size_t wstride, size_t pstride) {
    const float* W = W0 + blockIdx.z * wstride;
    uint32_t* Wh = Wh0 + blockIdx.z * pstride;
    uint32_t* Wl = Wl0 + blockIdx.z * pstride;
    __shared__ float2 tile[32][33];
    int kp0 = blockIdx.x * 32, n0 = blockIdx.y * 32;
    int tx = threadIdx.x, ty = threadIdx.y;   // 32 x 8
    #pragma unroll
    for (int j = 0; j < 4; j++) {
        int kp = kp0 + ty + j * 8, k = 2 * kp, n = n0 + tx;
        int on = n;
        if (ilv) on = (n & 1) ? (n >> 1) + DHID : (n >> 1);
        float a = 0.0f, b = 0.0f;
        if (n < N) {
            if (k < K)     a = W[(size_t)k * N + on];
            if (k + 1 < K) b = W[(size_t)(k + 1) * N + on];
        }
        tile[ty + j * 8][tx] = make_float2(a, b);
    }
    __syncthreads();
    #pragma unroll
    for (int j = 0; j < 4; j++) {
        int n = n0 + ty + j * 8, kp = kp0 + tx;
        if (n < N && kp < Kps) {
            float2 v = tile[tx][ty + j * 8];
            uint32_t hi, lo;
            split2(v.x, v.y, hi, lo);
            Wh[(size_t)n * Kps + kp] = hi;
            Wl[(size_t)n * Kps + kp] = lo;
        }
    }
}

// ---------------- rope table ----------------
__global__ void ropetab_k(float2* __restrict__ rt) {
    int idx = blockIdx.x * 256 + threadIdx.x;
    if (idx >= S_ * 32) return;
    int pair = idx & 31, pos = idx >> 5;
    float inv = expf(-logf(10000.0f) * (float)pair * (1.0f / 32.0f));
    float s, c;
    sincosf((float)pos * inv, &s, &c);
    rt[idx] = make_float2(c, s);
}

// ================= split-bf16 HMMA GEMM, double-buffered cp.async + ldmatrix ======
// template MT = m-tiles per warp (4 -> BM=128, 2 -> BM=64). BN=128.
#define BPL 2560
template<int MT>
__global__ void __launch_bounds__(256, 2) gemm_bs(
    int N, int Kp, int ldap, int ldbp, int ldc,
    const uint32_t* __restrict__ Agh, const uint32_t* __restrict__ Agl,
    const uint32_t* __restrict__ Bgh, const uint32_t* __restrict__ Bgl,
    float* __restrict__ C, const float* __restrict__ bias,
    const float* __restrict__ addsrc, int mode,
    uint32_t* __restrict__ Yh, uint32_t* __restrict__ Yl,
    const float2* __restrict__ rt, const float* __restrict__ mixp,
    float* __restrict__ fvp,
    uint32_t* __restrict__ Qh, uint32_t* __restrict__ Ql,
    uint32_t* __restrict__ Kh2, uint32_t* __restrict__ Kl2,
    uint32_t* __restrict__ Vh2, uint32_t* __restrict__ Vl2, int layer0)
{
    constexpr int BM  = MT * 32;
    constexpr int APL = BM * 20;           // u32 per A plane
    constexpr int STG = 2 * APL + 2 * BPL; // u32 per stage
    extern __shared__ uint32_t sm[];
    int tid = threadIdx.x;
    int wid = tid >> 5, lane = tid & 31;
    int m0 = blockIdx.y * BM, n0 = blockIdx.x * 128;
    int wm = (wid >> 2) * (MT * 16), wn = (wid & 3) * 32;
    int g = lane >> 2, t = lane & 3;

    float acc[MT][4][4];
    #pragma unroll
    for (int i = 0; i < MT; i++)
        #pragma unroll
        for (int j = 0; j < 4; j++)
            #pragma unroll
            for (int q = 0; q < 4; q++) acc[i][j][q] = 0.0f;

    uint32_t smb = smem_u32(sm);
    int nch = Kp >> 4;

    auto load_chunk = [&](int c, int buf) {
        int kp0 = c << 4;
        uint32_t base = smb + (uint32_t)buf * (STG * 4);
        #pragma unroll
        for (int i = 0; i < 2; i++) {
            int e = i * 256 + tid;
            int row = e >> 2, seg = (e & 3) * 4;
            uint32_t soff = (uint32_t)(row * 20 + seg) * 4;
            if (row < BM) {
                size_t aoff = (size_t)(m0 + row) * ldap + kp0 + seg;
                cp16(base + soff, Agh + aoff, 16);
                cp16(base + APL * 4 + soff, Agl + aoff, 16);
            }
            int nn = n0 + row;
            int sz = (nn < N) ? 16 : 0;
            size_t boff = (size_t)(nn < N ? nn : 0) * ldbp + kp0 + seg;
            cp16(base + 2 * APL * 4 + soff, Bgh + boff, sz);
            cp16(base + (2 * APL + BPL) * 4 + soff, Bgl + boff, sz);
        }
        asm volatile("cp.async.commit_group;" ::: "memory");
    };

    int a_row = lane & 15, a_colo = (lane >> 4) * 4;
    int b_l8 = lane & 7, b_seg = lane >> 3;

    load_chunk(0, 0);
    for (int c = 0; c < nch; c++) {
        if (c + 1 < nch) {
            load_chunk(c + 1, (c + 1) & 1);
            asm volatile("cp.async.wait_group 1;" ::: "memory");
        } else {
            asm volatile("cp.async.wait_group 0;" ::: "memory");
        }
        __syncthreads();

        uint32_t abh = smb + (uint32_t)(c & 1) * (STG * 4);
        uint32_t abl = abh + APL * 4;
        uint32_t bbh = abh + 2 * APL * 4;
        uint32_t bbl = bbh + BPL * 4;

        #pragma unroll
        for (int s = 0; s < 2; s++) {
            uint32_t afh[MT][4], afl[MT][4];
            #pragma unroll
            for (int mt = 0; mt < MT; mt++) {
                uint32_t off = (uint32_t)(((wm + mt * 16 + a_row) * 20 + s * 8 + a_colo) * 4);
                ldsm4(afh[mt][0], afh[mt][1], afh[mt][2], afh[mt][3], abh + off);
                ldsm4(afl[mt][0], afl[mt][1], afl[mt][2], afl[mt][3], abl + off);
            }
            uint32_t bfh[4][2], bfl[4][2];
            #pragma unroll
            for (int np = 0; np < 2; np++) {
                int brow = wn + (np * 2 + (b_seg >> 1)) * 8 + b_l8;
                int bcol = s * 8 + (b_seg & 1) * 4;
                uint32_t off = (uint32_t)((brow * 20 + bcol) * 4);
                ldsm4(bfh[np*2][0], bfh[np*2][1], bfh[np*2+1][0], bfh[np*2+1][1], bbh + off);
                ldsm4(bfl[np*2][0], bfl[np*2][1], bfl[np*2+1][0], bfl[np*2+1][1], bbl + off);
            }
            #pragma unroll
            for (int mt = 0; mt < MT; mt++)
                #pragma unroll
                for (int nt = 0; nt < 4; nt++) {
                    mma16816(acc[mt][nt], afh[mt], bfh[nt]);
                    mma16816(acc[mt][nt], afh[mt], bfl[nt]);
                    mma16816(acc[mt][nt], afl[mt], bfh[nt]);
                }
        }
        __syncthreads();
    }

    if (mode == 0) {
        #pragma unroll
        for (int mt = 0; mt < MT; mt++) {
            int r0 = m0 + wm + mt * 16 + g;
            #pragma unroll
            for (int nt = 0; nt < 4; nt++) {
                int col = n0 + wn + nt * 8 + 2 * t;
                #pragma unroll
                for (int half = 0; half < 2; half++) {
                    int row = r0 + half * 8;
                    float v0 = acc[mt][nt][half * 2 + 0];
                    float v1 = acc[mt][nt][half * 2 + 1];
                    if (col < N) {
                        if (bias)   v0 += bias[col];
                        if (addsrc) v0 += addsrc[(size_t)row * ldc + col];
                        C[(size_t)row * ldc + col] = v0;
                    }
                    if (col + 1 < N) {
                        if (bias)   v1 += bias[col + 1];
                        if (addsrc) v1 += addsrc[(size_t)row * ldc + col + 1];
                        C[(size_t)row * ldc + col + 1] = v1;
                    }
                }
            }
        }
    } else if (mode == 1) {
        #pragma unroll
        for (int mt = 0; mt < MT; mt++) {
            int r0 = m0 + wm + mt * 16 + g;
            #pragma unroll
            for (int nt = 0; nt < 4; nt++) {
                int col = n0 + wn + nt * 8 + 2 * t;
                int j = col >> 1;
                bool valid = col < N;
                #pragma unroll
                for (int half = 0; half < 2; half++) {
                    int row = r0 + half * 8;
                    float y = 0.0f;
                    if (valid) {
                        float a  = acc[mt][nt][half * 2 + 0] + bias[j];
                        float gg = acc[mt][nt][half * 2 + 1] + bias[j + DHID];
                        y = a * 0.5f * gg * (1.0f + erff(gg * 0.70710678118654752f));
                    }
                    float y1 = __shfl_down_sync(0xffffffffu, y, 1);
                    if ((t & 1) == 0) {
                        int kp = j >> 1;
                        if (kp < KPY) {
                            uint32_t hi, lo;
                            split2(y, y1, hi, lo);
                            Yh[(size_t)row * KPY + kp] = hi;
                            Yl[(size_t)row * KPY + kp] = lo;
                        }
                    }
                }
            }
        }
    } else {
        int region = n0 >> 9;   // 0=q, 1=k, 2=v
        #pragma unroll
        for (int mt = 0; mt < MT; mt++) {
            int r0 = m0 + wm + mt * 16 + g;
            #pragma unroll
            for (int nt = 0; nt < 4; nt++) {
                int col = n0 + wn + nt * 8 + 2 * t;
                int cc = col & 511;
                #pragma unroll
                for (int half = 0; half < 2; half++) {
                    int row = r0 + half * 8;
                    float v0 = acc[mt][nt][half * 2 + 0];
                    float v1 = acc[mt][nt][half * 2 + 1];
                    size_t idx = (size_t)row * KPX + (cc >> 1);
                    if (region <= 1) {
                        float2 cs = rt[(row & (S_ - 1)) * 32 + ((cc & 63) >> 1)];
                        float r1 = v0 * cs.x - v1 * cs.y;
                        float r2 = v0 * cs.y + v1 * cs.x;
                        if (region == 0) { r1 *= 0.125f; r2 *= 0.125f; }
                        uint32_t hi, lo;
                        split2(r1, r2, hi, lo);
                        if (region == 0) { Qh[idx] = hi; Ql[idx] = lo; }
                        else             { Kh2[idx] = hi; Kl2[idx] = lo; }
                    } else {
                        if (layer0) {
                            fvp[(size_t)row * DI + cc] = v0;
                            fvp[(size_t)row * DI + cc + 1] = v1;
                        } else {
                            float mx = mixp[(size_t)row * H_ + (cc >> 6)];
                            float f0 = fvp[(size_t)row * DI + cc];
                            float f1 = fvp[(size_t)row * DI + cc + 1];
                            v0 += mx * (f0 - v0);
                            v1 += mx * (f1 - v1);
                        }
                        uint32_t hi, lo;
                        split2(v0, v1, hi, lo);
                        Vh2[idx] = hi; Vl2[idx] = lo;
                    }
                }
            }
        }
    }
}

// ================= flash attention: Br=128, double-buffered cp.async tiles ========
// heavy-first scheduling: Qb = gridDim.x-1-blockIdx.x (LPT makespan on skewed work)
#define ATSM_PL  2304    // uint32 per plane (64*36)
#define ATSM_BUF 9216    // uint32 per buffer (4 planes)
__global__ void __launch_bounds__(256) attn_mma(
    const uint32_t* __restrict__ Qh, const uint32_t* __restrict__ Ql,
    const uint32_t* __restrict__ Kg_h, const uint32_t* __restrict__ Kg_l,
    const uint32_t* __restrict__ Vg_h, const uint32_t* __restrict__ Vg_l,
    uint32_t* __restrict__ Oh, uint32_t* __restrict__ Ol)
{
    extern __shared__ uint32_t asmem[];
    int Qb = gridDim.x - 1 - blockIdx.x;   // 128-row query tile, heavy-first
    int h  = blockIdx.y & 7, b = blockIdx.y >> 3;
    int tid = threadIdx.x, w = tid >> 5, lane = tid & 31;
    int g = lane >> 2, t = lane & 3;
    int row0 = b * S_ + Qb * 128;

    uint32_t base = smem_u32(asmem);
    int l8 = lane & 7, seg8 = lane >> 3;

    auto load_tile = [&](int J, int buf) {
        int kr = b * S_ + J * 64;
        uint32_t bb = base + (uint32_t)buf * (ATSM_BUF * 4);
        #pragma unroll
        for (int i = 0; i < 2; i++) {
            int cc = i * 256 + tid;          // 0..511
            int row = cc >> 3, sg = cc & 7;
            size_t src = (size_t)(kr + row) * KPX + h * 32 + sg * 4;
            uint32_t soff = (uint32_t)(row * 36 + sg * 4) * 4;
            cp16(bb + soff, Kg_h + src, 16);
            cp16(bb + ATSM_PL * 4 + soff, Kg_l + src, 16);
            cp16(bb + ATSM_PL * 8 + soff, Vg_h + src, 16);
            cp16(bb + ATSM_PL * 12 + soff, Vg_l + src, 16);
        }
        asm volatile("cp.async.commit_group;" ::: "memory");
    };

    uint32_t qh[4][4], ql[4][4];
    #pragma unroll
    for (int kt = 0; kt < 4; kt++) {
        #pragma unroll
        for (int q = 0; q < 4; q++) {
            int rr = row0 + w * 16 + g + ((q & 1) ? 8 : 0);
            int kp = kt * 8 + t + ((q & 2) ? 4 : 0);
            size_t idx = (size_t)rr * KPX + h * 32 + kp;
            qh[kt][q] = Qh[idx];
            ql[kt][q] = Ql[idx];
        }
    }

    float Oa[8][4];
    #pragma unroll
    for (int i = 0; i < 8; i++)
        #pragma unroll
        for (int q = 0; q < 4; q++) Oa[i][q] = 0.0f;
    float m_[2] = {-INFINITY, -INFINITY};
    float l_[2] = {0.0f, 0.0f};

    int Jmax = 2 * Qb + 1;
    load_tile(0, 0);
    for (int J = 0; J <= Jmax; J++) {
        if (J < Jmax) {
            load_tile(J + 1, (J + 1) & 1);
            asm volatile("cp.async.wait_group 1;" ::: "memory");
        } else {
            asm volatile("cp.async.wait_group 0;" ::: "memory");
        }
        __syncthreads();

        uint32_t kbh = base + (uint32_t)(J & 1) * (ATSM_BUF * 4);
        uint32_t kbl = kbh + ATSM_PL * 4;
        uint32_t vbh = kbh + ATSM_PL * 8;
        uint32_t vbl = kbh + ATSM_PL * 12;

        int ntS = 8;
        if (J == 2 * Qb)       { if (w < 2) ntS = 4; }
        else if (J == Jmax)    { ntS = (w < 4) ? 0 : ((w < 6) ? 4 : 8); }

        if (ntS > 0) {
            int ktPV = ntS >> 1;

            float Sa[8][4];
            for (int nt = 0; nt < ntS; nt++) {
                Sa[nt][0] = Sa[nt][1] = Sa[nt][2] = Sa[nt][3] = 0.0f;
                uint32_t kfh[4][2], kfl[4][2];
                uint32_t off0 = (uint32_t)(((8 * nt + l8) * 36 + seg8 * 4) * 4);
                ldsm4(kfh[0][0], kfh[0][1], kfh[1][0], kfh[1][1], kbh + off0);
                ldsm4(kfh[2][0], kfh[2][1], kfh[3][0], kfh[3][1], kbh + off0 + 64);
                ldsm4(kfl[0][0], kfl[0][1], kfl[1][0], kfl[1][1], kbl + off0);
                ldsm4(kfl[2][0], kfl[2][1], kfl[3][0], kfl[3][1], kbl + off0 + 64);
                #pragma unroll
                for (int kt = 0; kt < 4; kt++) {
                    mma16816(Sa[nt], qh[kt], kfh[kt]);
                    mma16816(Sa[nt], qh[kt], kfl[kt]);
                    mma16816(Sa[nt], ql[kt], kfh[kt]);
                }
            }

            float alpha[2];
            #pragma unroll
            for (int half = 0; half < 2; half++) {
                float mx = -INFINITY;
                for (int nt = 0; nt < ntS; nt++) {
                    mx = fmaxf(mx, Sa[nt][half * 2]);
                    mx = fmaxf(mx, Sa[nt][half * 2 + 1]);
                }
                mx = fmaxf(mx, __shfl_xor_sync(0xffffffffu, mx, 1));
                mx = fmaxf(mx, __shfl_xor_sync(0xffffffffu, mx, 2));
                float mn = fmaxf(m_[half], mx);
                alpha[half] = __expf(m_[half] - mn);
                m_[half] = mn;
                float ps = 0.0f;
                for (int nt = 0; nt < ntS; nt++) {
                    float p0 = __expf(Sa[nt][half * 2]     - mn);
                    float p1 = __expf(Sa[nt][half * 2 + 1] - mn);
                    Sa[nt][half * 2]     = p0;
                    Sa[nt][half * 2 + 1] = p1;
                    ps += p0 + p1;
                }
                l_[half] = l_[half] * alpha[half] + ps;
            }
            #pragma unroll
            for (int nt = 0; nt < 8; nt++) {
                Oa[nt][0] *= alpha[0]; Oa[nt][1] *= alpha[0];
                Oa[nt][2] *= alpha[1]; Oa[nt][3] *= alpha[1];
            }

            uint32_t ph[4][4], pl[4][4];
            for (int kt = 0; kt < ktPV; kt++) {
                split2(Sa[2 * kt][0],     Sa[2 * kt][1],     ph[kt][0], pl[kt][0]);
                split2(Sa[2 * kt][2],     Sa[2 * kt][3],     ph[kt][1], pl[kt][1]);
                split2(Sa[2 * kt + 1][0], Sa[2 * kt + 1][1], ph[kt][2], pl[kt][2]);
                split2(Sa[2 * kt + 1][2], Sa[2 * kt + 1][3], ph[kt][3], pl[kt][3]);
            }

            int npair = ktPV >> 1;
            for (int p = 0; p < npair; p++) {
                int key = 32 * p + seg8 * 8 + l8;
                #pragma unroll
                for (int nt = 0; nt < 8; nt++) {
                    uint32_t off = (uint32_t)((key * 36 + nt * 4) * 4);
                    uint32_t bh0, bh1, bh2, bh3, bl0, bl1, bl2, bl3;
                    ldsm4t(bh0, bh1, bh2, bh3, vbh + off);
                    ldsm4t(bl0, bl1, bl2, bl3, vbl + off);
                    uint32_t b0h[2] = {bh0, bh1}, b0l[2] = {bl0, bl1};
                    uint32_t b1h[2] = {bh2, bh3}, b1l[2] = {bl2, bl3};
                    mma16816(Oa[nt], ph[2*p],     b0h);
                    mma16816(Oa[nt], ph[2*p],     b0l);
                    mma16816(Oa[nt], pl[2*p],     b0h);
                    mma16816(Oa[nt], ph[2*p + 1], b1h);
                    mma16816(Oa[nt], ph[2*p + 1], b1l);
                    mma16816(Oa[nt], pl[2*p + 1], b1h);
                }
            }
        }
        __syncthreads();
    }

    float linv[2];
    #pragma unroll
    for (int half = 0; half < 2; half++) {
        float l = l_[half];
        l += __shfl_xor_sync(0xffffffffu, l, 1);
        l += __shfl_xor_sync(0xffffffffu, l, 2);
        linv[half] = 1.0f / l;
    }
    int r0 = w * 16 + g, r1 = r0 + 8;
    #pragma unroll
    for (int nt = 0; nt < 8; nt++) {
        int kp = h * 32 + 4 * nt + t;
        uint32_t hi, lo;
        split2(Oa[nt][0] * linv[0], Oa[nt][1] * linv[0], hi, lo);
        Oh[(size_t)(row0 + r0) * KPX + kp] = hi;
        Ol[(size_t)(row0 + r0) * KPX + kp] = lo;
        split2(Oa[nt][2] * linv[1], Oa[nt][3] * linv[1], hi, lo);
        Oh[(size_t)(row0 + r1) * KPX + kp] = hi;
        Ol[(size_t)(row0 + r1) * KPX + kp] = lo;
    }
}

// ---------------- rmsnorm -> split output ----------------
__global__ void rmsnorm_split_k(const float* __restrict__ in, const float* __restrict__ w,
                                uint32_t* __restrict__ Xh, uint32_t* __restrict__ Xl) {
    int row = blockIdx.x;
    const float4* ip = (const float4*)(in + (size_t)row * D_);
    float4 v = ip[threadIdx.x];
    float ss = v.x*v.x + v.y*v.y + v.z*v.z + v.w*v.w;
    #pragma unroll
    for (int o = 16; o; o >>= 1) ss += __shfl_xor_sync(0xffffffffu, ss, o);
    __shared__ float sred[4];
    if ((threadIdx.x & 31) == 0) sred[threadIdx.x >> 5] = ss;
    __syncthreads();
    float tot = sred[0] + sred[1] + sred[2] + sred[3];
    float sc = rsqrtf(tot * (1.0f / 512.0f) + 1.1920929e-7f);
    const float4* wp = (const float4*)w;
    float4 wv = wp[threadIdx.x];
    float o0 = v.x * sc * wv.x, o1 = v.y * sc * wv.y;
    float o2 = v.z * sc * wv.z, o3 = v.w * sc * wv.w;
    uint32_t h0, l0, h1, l1;
    split2(o0, o1, h0, l0);
    split2(o2, o3, h1, l1);
    size_t base = (size_t)row * KPX + threadIdx.x * 2;
    Xh[base] = h0; Xh[base + 1] = h1;
    Xl[base] = l0; Xl[base + 1] = l1;
}

// ---------------- mix gate ----------------
__global__ void mix_k(const uint32_t* __restrict__ Xh, const uint32_t* __restrict__ Xl,
                      const float* __restrict__ mw, const float* __restrict__ mb,
                      float* __restrict__ mix) {
    int row = blockIdx.x;
    int lane = threadIdx.x & 31;
    int h = threadIdx.x >> 5;
    float dot = 0.0f;
    #pragma unroll
    for (int kp = lane; kp < KPX; kp += 32) {
        uint32_t hv = Xh[(size_t)row * KPX + kp], lv = Xl[(size_t)row * KPX + kp];
        float x0 = __uint_as_float(hv << 16) + __uint_as_float(lv << 16);
        float x1 = __uint_as_float(hv & 0xFFFF0000u) + __uint_as_float(lv & 0xFFFF0000u);
        dot += x0 * mw[(2 * kp) * H_ + h] + x1 * mw[(2 * kp + 1) * H_ + h];
    }
    #pragma unroll
    for (int o = 16; o; o >>= 1) dot += __shfl_xor_sync(0xffffffffu, dot, o);
    if (lane == 0)
        mix[(size_t)row * H_ + h] = 1.0f / (1.0f + expf(-(dot + mb[h])));
}

// ---------------- rmsnorm fp32 out (final) ----------------
__global__ void rmsnorm_k(const float* __restrict__ in, const float* __restrict__ w,
                          float* __restrict__ out) {
    int row = blockIdx.x;
    const float4* ip = (const float4*)(in + (size_t)row * D_);
    float4 v = ip[threadIdx.x];
    float ss = v.x*v.x + v.y*v.y + v.z*v.z + v.w*v.w;
    #pragma unroll
    for (int o = 16; o; o >>= 1) ss += __shfl_xor_sync(0xffffffffu, ss, o);
    __shared__ float sred[4];
    if ((threadIdx.x & 31) == 0) sred[threadIdx.x >> 5] = ss;
    __syncthreads();
    float tot = sred[0] + sred[1] + sred[2] + sred[3];
    float sc = rsqrtf(tot * (1.0f / 512.0f) + 1.1920929e-7f);
    const float4* wp = (const float4*)w;
    float4 wv = wp[threadIdx.x];
    float4 o4;
    o4.x = v.x * sc * wv.x; o4.y = v.y * sc * wv.y;
    o4.z = v.z * sc * wv.z; o4.w = v.w * sc * wv.w;
    ((float4*)(out + (size_t)row * D_))[threadIdx.x] = o4;
}

// ---------------- launch ----------------
extern "C" void kernel_launch(void* const* d_in, const int* in_sizes, int n_in,
                              void* d_out, int out_size) {
    const float* tokens       = (const float*)d_in[0];
    const float* attn_norm_w  = (const float*)d_in[1];
    const float* qkv_w        = (const float*)d_in[2];
    const float* out_w        = (const float*)d_in[3];
    const float* mix_w        = (const float*)d_in[4];
    const float* mix_b        = (const float*)d_in[5];
    const float* ff_norm_w    = (const float*)d_in[6];
    const float* ff_in_w      = (const float*)d_in[7];
    const float* ff_in_b      = (const float*)d_in[8];
    const float* ff_out_w     = (const float*)d_in[9];
    const float* ff_out_b     = (const float*)d_in[10];
    const float* final_norm_w = (const float*)d_in[11];

    float *t_, *fv_, *mix_;
    float2* rt_;
    uint32_t *xh_, *xl_, *oh_, *ol_, *yh_, *yl_;
    uint32_t *qh2_, *ql2_, *kh2_, *kl2_, *vh2_, *vl2_;
    uint32_t *wqh_, *wql_, *woh_, *wol_, *wfh_, *wfl_, *wgh_, *wgl_;
    cudaGetSymbolAddress((void**)&t_,   g_t);
    cudaGetSymbolAddress((void**)&fv_,  g_fv);
    cudaGetSymbolAddress((void**)&mix_, g_mix);
    cudaGetSymbolAddress((void**)&rt_,  g_rt);
    cudaGetSymbolAddress((void**)&xh_,  g_xh);
    cudaGetSymbolAddress((void**)&xl_,  g_xl);
    cudaGetSymbolAddress((void**)&oh_,  g_oh);
    cudaGetSymbolAddress((void**)&ol_,  g_ol);
    cudaGetSymbolAddress((void**)&yh_,  g_yh);
    cudaGetSymbolAddress((void**)&yl_,  g_yl);
    cudaGetSymbolAddress((void**)&qh2_, g_qh2);
    cudaGetSymbolAddress((void**)&ql2_, g_ql2);
    cudaGetSymbolAddress((void**)&kh2_, g_kh2);
    cudaGetSymbolAddress((void**)&kl2_, g_kl2);
    cudaGetSymbolAddress((void**)&vh2_, g_vh2);
    cudaGetSymbolAddress((void**)&vl2_, g_vl2);
    cudaGetSymbolAddress((void**)&wqh_, g_wqh);
    cudaGetSymbolAddress((void**)&wql_, g_wql);
    cudaGetSymbolAddress((void**)&woh_, g_woh);
    cudaGetSymbolAddress((void**)&wol_, g_wol);
    cudaGetSymbolAddress((void**)&wfh_, g_wfh);
    cudaGetSymbolAddress((void**)&wfl_, g_wfl);
    cudaGetSymbolAddress((void**)&wgh_, g_wgh);
    cudaGetSymbolAddress((void**)&wgl_, g_wgl);

    const int GSM4 = 2 * (2 * 128 * 20 + 2 * BPL) * 4;   // 81920
    const int GSM2 = 2 * (2 * 64 * 20 + 2 * BPL) * 4;    // 61440
    const int ASM  = 2 * ATSM_BUF * 4;
    static int smem_set = 0;
    if (!smem_set) {
        cudaFuncSetAttribute(gemm_bs<4>, cudaFuncAttributeMaxDynamicSharedMemorySize, GSM4);
        cudaFuncSetAttribute(gemm_bs<2>, cudaFuncAttributeMaxDynamicSharedMemorySize, GSM2);
        cudaFuncSetAttribute(attn_mma, cudaFuncAttributeMaxDynamicSharedMemorySize, ASM);
        smem_set = 1;
    }

    ropetab_k<<<(S_ * 32 + 255) / 256, 256>>>(rt_);

    dim3 cb(32, 8);
    wconv_k<<<dim3(KPX / 32, QKVN / 32, L_), cb>>>(
        qkv_w, wqh_, wql_, D_, QKVN, KPX, 0,
        (size_t)D_ * QKVN, (size_t)QKVN * KPX);
    wconv_k<<<dim3(KPX / 32, DI / 32, L_), cb>>>(
        out_w, woh_, wol_, DI, D_, KPX, 0,
        (size_t)DI * D_, (size_t)DI * KPX);
    wconv_k<<<dim3(KPX / 32, (FFN + 31) / 32, L_), cb>>>(
        ff_in_w, wfh_, wfl_, D_, FFN, KPX, 1,
        (size_t)D_ * FFN, (size_t)FFN * KPX);
    wconv_k<<<dim3((KPY + 31) / 32, DI / 32, L_), cb>>>(
        ff_out_w, wgh_, wgl_, DHID, D_, KPY, 0,
        (size_t)DHID * D_, (size_t)DI * KPY);

    for (int l = 0; l < L_; l++) {
        const float* res_in = (l == 0) ? tokens : t_;

        rmsnorm_split_k<<<M_, 128>>>(res_in, attn_norm_w + l * D_, xh_, xl_);

        if (l > 0)
            mix_k<<<M_, 256>>>(xh_, xl_, mix_w + (size_t)l * D_ * H_, mix_b + l * H_, mix_);

        gemm_bs<4><<<dim3(QKVN / 128, M_ / 128), 256, GSM4>>>(
            QKVN, KPX, KPX, KPX, 0,
            xh_, xl_, wqh_ + (size_t)l * QKVN * KPX, wql_ + (size_t)l * QKVN * KPX,
            nullptr, nullptr, nullptr, 2, nullptr, nullptr,
            rt_, mix_, fv_, qh2_, ql2_, kh2_, kl2_, vh2_, vl2_, (l == 0) ? 1 : 0);

        attn_mma<<<dim3(S_ / 128, B_ * H_), 256, ASM>>>(
            qh2_, ql2_, kh2_, kl2_, vh2_, vl2_, oh_, ol_);

        gemm_bs<2><<<dim3(D_ / 128, M_ / 64), 256, GSM2>>>(
            D_, KPX, KPX, KPX, D_,
            oh_, ol_, woh_ + (size_t)l * DI * KPX, wol_ + (size_t)l * DI * KPX,
            t_, nullptr, res_in, 0, nullptr, nullptr,
            nullptr, nullptr, nullptr, nullptr, nullptr, nullptr, nullptr, nullptr, nullptr, 0);

        rmsnorm_split_k<<<M_, 128>>>(t_, ff_norm_w + l * D_, xh_, xl_);

        gemm_bs<4><<<dim3((FFN + 127) / 128, M_ / 128), 256, GSM4>>>(
            FFN, KPX, KPX, KPX, 0,
            xh_, xl_, wfh_ + (size_t)l * FFN * KPX, wfl_ + (size_t)l * FFN * KPX,
            nullptr, ff_in_b + (size_t)l * FFN, nullptr, 1, yh_, yl_,
            nullptr, nullptr, nullptr, nullptr, nullptr, nullptr, nullptr, nullptr, nullptr, 0);

        gemm_bs<2><<<dim3(D_ / 128, M_ / 64), 256, GSM2>>>(
            D_, KPY, KPY, KPY, D_,
            yh_, yl_, wgh_ + (size_t)l * DI * KPY, wgl_ + (size_t)l * DI * KPY,
            t_, ff_out_b + (size_t)l * D_, t_, 0, nullptr, nullptr,
            nullptr, nullptr, nullptr, nullptr, nullptr, nullptr, nullptr, nullptr, nullptr, 0);
    }

    rmsnorm_k<<<M_, 128>>>(t_, final_norm_w, (float*)d_out);
}

// round 17
// speedup vs baseline: 1.1535x; 1.0808x over previous
#include <cuda_runtime.h>
#include <cuda_bf16.h>
#include <math.h>
#include <stdint.h>

#define B_   2
#define S_   2048
#define D_   512
#define L_   4
#define H_   8
#define DH   64
#define M_   (B_*S_)      // 4096 rows
#define DI   512          // H*DH
#define QKVN 1536
#define DHID 1365
#define FFN  2730         // 2*DHID
#define KPX  256          // k-pairs for K=512
#define KPY  688          // k-pairs (padded) for K=1365

// ---------------- scratch (no allocation allowed) ----------------
__device__ float    g_t   [M_ * D_];            // residual stream
__device__ float    g_fv  [M_ * DI];            // first layer's v (fp32)
__device__ float    g_mix [M_ * H_];            // sigmoid gates
__device__ float2   g_rt  [S_ * 32];            // rope cos/sin table
__device__ uint32_t g_xh  [M_ * KPX], g_xl [M_ * KPX];   // rmsnorm out (split)
__device__ uint32_t g_oh  [M_ * KPX], g_ol [M_ * KPX];   // attn out (split)
__device__ uint32_t g_yh  [M_ * KPY], g_yl [M_ * KPY];   // gelu out (split; padding stays 0)
__device__ uint32_t g_qh2 [M_ * KPX], g_ql2 [M_ * KPX];  // roped+scaled q (split)
__device__ uint32_t g_kh2 [M_ * KPX], g_kl2 [M_ * KPX];  // roped k (split)
__device__ uint32_t g_vh2 [M_ * KPX], g_vl2 [M_ * KPX];  // mixed v (split)
// converted weights (transposed [N][Kp], hi/lo planes)
__device__ uint32_t g_wqh [L_ * QKVN * KPX], g_wql [L_ * QKVN * KPX];
__device__ uint32_t g_woh [L_ * DI   * KPX], g_wol [L_ * DI   * KPX];
__device__ uint32_t g_wfh [L_ * FFN  * KPX], g_wfl [L_ * FFN  * KPX];
__device__ uint32_t g_wgh [L_ * DI   * KPY], g_wgl [L_ * DI   * KPY];

// ---------------- helpers ----------------
__device__ __forceinline__ uint32_t smem_u32(const void* p) {
    uint32_t a;
    asm("{ .reg .u64 t; cvta.to.shared.u64 t, %1; cvt.u32.u64 %0, t; }" : "=r"(a) : "l"(p));
    return a;
}
__device__ __forceinline__ uint32_t pack_bf(float x, float y) {
    uint32_t r;
    asm("cvt.rn.bf16x2.f32 %0, %1, %2;" : "=r"(r) : "f"(y), "f"(x));
    return r;
}
__device__ __forceinline__ void split2(float x, float y, uint32_t& hi, uint32_t& lo) {
    hi = pack_bf(x, y);
    float rx = x - __uint_as_float(hi << 16);
    float ry = y - __uint_as_float(hi & 0xFFFF0000u);
    lo = pack_bf(rx, ry);
}
__device__ __forceinline__ void mma16816(float* c, const uint32_t* a, const uint32_t* b) {
    asm volatile(
        "mma.sync.aligned.m16n8k16.row.col.f32.bf16.bf16.f32 "
        "{%0,%1,%2,%3}, {%4,%5,%6,%7}, {%8,%9}, {%0,%1,%2,%3};"
        : "+f"(c[0]), "+f"(c[1]), "+f"(c[2]), "+f"(c[3])
        : "r"(a[0]), "r"(a[1]), "r"(a[2]), "r"(a[3]), "r"(b[0]), "r"(b[1]));
}
__device__ __forceinline__ void ldsm4(uint32_t& r0, uint32_t& r1, uint32_t& r2, uint32_t& r3,
                                      uint32_t addr) {
    asm volatile("ldmatrix.sync.aligned.m8n8.x4.shared.b16 {%0,%1,%2,%3}, [%4];"
                 : "=r"(r0), "=r"(r1), "=r"(r2), "=r"(r3) : "r"(addr));
}
__device__ __forceinline__ void ldsm4t(uint32_t& r0, uint32_t& r1, uint32_t& r2, uint32_t& r3,
                                       uint32_t addr) {
    asm volatile("ldmatrix.sync.aligned.m8n8.x4.trans.shared.b16 {%0,%1,%2,%3}, [%4];"
                 : "=r"(r0), "=r"(r1), "=r"(r2), "=r"(r3) : "r"(addr));
}
__device__ __forceinline__ void cp16(uint32_t dst, const void* src, int sz) {
    asm volatile("cp.async.ca.shared.global [%0], [%1], 16, %2;"
                 :: "r"(dst), "l"(src), "r"(sz) : "memory");
}

// ---------------- weight convert: W[K][N] fp32 -> Wh/Wl [N][Kps]; z = layer --------
__global__ void wconv_k(const float* __restrict__ W0, uint32_t* __restrict__ Wh0,
                        uint32_t* __restrict__ Wl0, int K, int N, int Kps, int ilv,
                        size_t wstride, size_t pstride) {
    const float* W = W0 + blockIdx.z * wstride;
    uint32_t* Wh = Wh0 + blockIdx.z * pstride;
    uint32_t* Wl = Wl0 + blockIdx.z * pstride;
    __shared__ float2 tile[32][33];
    int kp0 = blockIdx.x * 32, n0 = blockIdx.y * 32;
    int tx = threadIdx.x, ty = threadIdx.y;   // 32 x 8
    #pragma unroll
    for (int j = 0; j < 4; j++) {
        int kp = kp0 + ty + j * 8, k = 2 * kp, n = n0 + tx;
        int on = n;
        if (ilv) on = (n & 1) ? (n >> 1) + DHID : (n >> 1);
        float a = 0.0f, b = 0.0f;
        if (n < N) {
            if (k < K)     a = W[(size_t)k * N + on];
            if (k + 1 < K) b = W[(size_t)(k + 1) * N + on];
        }
        tile[ty + j * 8][tx] = make_float2(a, b);
    }
    __syncthreads();
    #pragma unroll
    for (int j = 0; j < 4; j++) {
        int n = n0 + ty + j * 8, kp = kp0 + tx;
        if (n < N && kp < Kps) {
            float2 v = tile[tx][ty + j * 8];
            uint32_t hi, lo;
            split2(v.x, v.y, hi, lo);
            Wh[(size_t)n * Kps + kp] = hi;
            Wl[(size_t)n * Kps + kp] = lo;
        }
    }
}

// ---------------- rope table ----------------
__global__ void ropetab_k(float2* __restrict__ rt) {
    int idx = blockIdx.x * 256 + threadIdx.x;
    if (idx >= S_ * 32) return;
    int pair = idx & 31, pos = idx >> 5;
    float inv = expf(-logf(10000.0f) * (float)pair * (1.0f / 32.0f));
    float s, c;
    sincosf((float)pos * inv, &s, &c);
    rt[idx] = make_float2(c, s);
}

// ================= split-bf16 HMMA GEMM, double-buffered cp.async + ldmatrix ======
// template MT = m-tiles per warp (4 -> BM=128, 2 -> BM=64). BN=128.
#define BPL 2560
template<int MT>
__global__ void __launch_bounds__(256, 2) gemm_bs(
    int N, int Kp, int ldap, int ldbp, int ldc,
    const uint32_t* __restrict__ Agh, const uint32_t* __restrict__ Agl,
    const uint32_t* __restrict__ Bgh, const uint32_t* __restrict__ Bgl,
    float* __restrict__ C, const float* __restrict__ bias,
    const float* __restrict__ addsrc, int mode,
    uint32_t* __restrict__ Yh, uint32_t* __restrict__ Yl,
    const float2* __restrict__ rt, const float* __restrict__ mixp,
    float* __restrict__ fvp,
    uint32_t* __restrict__ Qh, uint32_t* __restrict__ Ql,
    uint32_t* __restrict__ Kh2, uint32_t* __restrict__ Kl2,
    uint32_t* __restrict__ Vh2, uint32_t* __restrict__ Vl2, int layer0)
{
    constexpr int BM  = MT * 32;
    constexpr int APL = BM * 20;           // u32 per A plane
    constexpr int STG = 2 * APL + 2 * BPL; // u32 per stage
    extern __shared__ uint32_t sm[];
    int tid = threadIdx.x;
    int wid = tid >> 5, lane = tid & 31;
    int m0 = blockIdx.y * BM, n0 = blockIdx.x * 128;
    int wm = (wid >> 2) * (MT * 16), wn = (wid & 3) * 32;
    int g = lane >> 2, t = lane & 3;

    float acc[MT][4][4];
    #pragma unroll
    for (int i = 0; i < MT; i++)
        #pragma unroll
        for (int j = 0; j < 4; j++)
            #pragma unroll
            for (int q = 0; q < 4; q++) acc[i][j][q] = 0.0f;

    uint32_t smb = smem_u32(sm);
    int nch = Kp >> 4;

    auto load_chunk = [&](int c, int buf) {
        int kp0 = c << 4;
        uint32_t base = smb + (uint32_t)buf * (STG * 4);
        #pragma unroll
        for (int i = 0; i < 2; i++) {
            int e = i * 256 + tid;
            int row = e >> 2, seg = (e & 3) * 4;
            uint32_t soff = (uint32_t)(row * 20 + seg) * 4;
            if (row < BM) {
                size_t aoff = (size_t)(m0 + row) * ldap + kp0 + seg;
                cp16(base + soff, Agh + aoff, 16);
                cp16(base + APL * 4 + soff, Agl + aoff, 16);
            }
            int nn = n0 + row;
            int sz = (nn < N) ? 16 : 0;
            size_t boff = (size_t)(nn < N ? nn : 0) * ldbp + kp0 + seg;
            cp16(base + 2 * APL * 4 + soff, Bgh + boff, sz);
            cp16(base + (2 * APL + BPL) * 4 + soff, Bgl + boff, sz);
        }
        asm volatile("cp.async.commit_group;" ::: "memory");
    };

    int a_row = lane & 15, a_colo = (lane >> 4) * 4;
    int b_l8 = lane & 7, b_seg = lane >> 3;

    load_chunk(0, 0);
    for (int c = 0; c < nch; c++) {
        if (c + 1 < nch) {
            load_chunk(c + 1, (c + 1) & 1);
            asm volatile("cp.async.wait_group 1;" ::: "memory");
        } else {
            asm volatile("cp.async.wait_group 0;" ::: "memory");
        }
        __syncthreads();

        uint32_t abh = smb + (uint32_t)(c & 1) * (STG * 4);
        uint32_t abl = abh + APL * 4;
        uint32_t bbh = abh + 2 * APL * 4;
        uint32_t bbl = bbh + BPL * 4;

        #pragma unroll
        for (int s = 0; s < 2; s++) {
            uint32_t afh[MT][4], afl[MT][4];
            #pragma unroll
            for (int mt = 0; mt < MT; mt++) {
                uint32_t off = (uint32_t)(((wm + mt * 16 + a_row) * 20 + s * 8 + a_colo) * 4);
                ldsm4(afh[mt][0], afh[mt][1], afh[mt][2], afh[mt][3], abh + off);
                ldsm4(afl[mt][0], afl[mt][1], afl[mt][2], afl[mt][3], abl + off);
            }
            uint32_t bfh[4][2], bfl[4][2];
            #pragma unroll
            for (int np = 0; np < 2; np++) {
                int brow = wn + (np * 2 + (b_seg >> 1)) * 8 + b_l8;
                int bcol = s * 8 + (b_seg & 1) * 4;
                uint32_t off = (uint32_t)((brow * 20 + bcol) * 4);
                ldsm4(bfh[np*2][0], bfh[np*2][1], bfh[np*2+1][0], bfh[np*2+1][1], bbh + off);
                ldsm4(bfl[np*2][0], bfl[np*2][1], bfl[np*2+1][0], bfl[np*2+1][1], bbl + off);
            }
            #pragma unroll
            for (int mt = 0; mt < MT; mt++)
                #pragma unroll
                for (int nt = 0; nt < 4; nt++) {
                    mma16816(acc[mt][nt], afh[mt], bfh[nt]);
                    mma16816(acc[mt][nt], afh[mt], bfl[nt]);
                    mma16816(acc[mt][nt], afl[mt], bfh[nt]);
                }
        }
        __syncthreads();
    }

    if (mode == 0) {
        #pragma unroll
        for (int mt = 0; mt < MT; mt++) {
            int r0 = m0 + wm + mt * 16 + g;
            #pragma unroll
            for (int nt = 0; nt < 4; nt++) {
                int col = n0 + wn + nt * 8 + 2 * t;
                #pragma unroll
                for (int half = 0; half < 2; half++) {
                    int row = r0 + half * 8;
                    float v0 = acc[mt][nt][half * 2 + 0];
                    float v1 = acc[mt][nt][half * 2 + 1];
                    if (col < N) {
                        if (bias)   v0 += bias[col];
                        if (addsrc) v0 += addsrc[(size_t)row * ldc + col];
                        C[(size_t)row * ldc + col] = v0;
                    }
                    if (col + 1 < N) {
                        if (bias)   v1 += bias[col + 1];
                        if (addsrc) v1 += addsrc[(size_t)row * ldc + col + 1];
                        C[(size_t)row * ldc + col + 1] = v1;
                    }
                }
            }
        }
    } else if (mode == 1) {
        #pragma unroll
        for (int mt = 0; mt < MT; mt++) {
            int r0 = m0 + wm + mt * 16 + g;
            #pragma unroll
            for (int nt = 0; nt < 4; nt++) {
                int col = n0 + wn + nt * 8 + 2 * t;
                int j = col >> 1;
                bool valid = col < N;
                #pragma unroll
                for (int half = 0; half < 2; half++) {
                    int row = r0 + half * 8;
                    float y = 0.0f;
                    if (valid) {
                        float a  = acc[mt][nt][half * 2 + 0] + bias[j];
                        float gg = acc[mt][nt][half * 2 + 1] + bias[j + DHID];
                        y = a * 0.5f * gg * (1.0f + erff(gg * 0.70710678118654752f));
                    }
                    float y1 = __shfl_down_sync(0xffffffffu, y, 1);
                    if ((t & 1) == 0) {
                        int kp = j >> 1;
                        if (kp < KPY) {
                            uint32_t hi, lo;
                            split2(y, y1, hi, lo);
                            Yh[(size_t)row * KPY + kp] = hi;
                            Yl[(size_t)row * KPY + kp] = lo;
                        }
                    }
                }
            }
        }
    } else {
        int region = n0 >> 9;   // 0=q, 1=k, 2=v
        #pragma unroll
        for (int mt = 0; mt < MT; mt++) {
            int r0 = m0 + wm + mt * 16 + g;
            #pragma unroll
            for (int nt = 0; nt < 4; nt++) {
                int col = n0 + wn + nt * 8 + 2 * t;
                int cc = col & 511;
                #pragma unroll
                for (int half = 0; half < 2; half++) {
                    int row = r0 + half * 8;
                    float v0 = acc[mt][nt][half * 2 + 0];
                    float v1 = acc[mt][nt][half * 2 + 1];
                    size_t idx = (size_t)row * KPX + (cc >> 1);
                    if (region <= 1) {
                        float2 cs = rt[(row & (S_ - 1)) * 32 + ((cc & 63) >> 1)];
                        float r1 = v0 * cs.x - v1 * cs.y;
                        float r2 = v0 * cs.y + v1 * cs.x;
                        if (region == 0) { r1 *= 0.125f; r2 *= 0.125f; }
                        uint32_t hi, lo;
                        split2(r1, r2, hi, lo);
                        if (region == 0) { Qh[idx] = hi; Ql[idx] = lo; }
                        else             { Kh2[idx] = hi; Kl2[idx] = lo; }
                    } else {
                        if (layer0) {
                            fvp[(size_t)row * DI + cc] = v0;
                            fvp[(size_t)row * DI + cc + 1] = v1;
                        } else {
                            float mx = mixp[(size_t)row * H_ + (cc >> 6)];
                            float f0 = fvp[(size_t)row * DI + cc];
                            float f1 = fvp[(size_t)row * DI + cc + 1];
                            v0 += mx * (f0 - v0);
                            v1 += mx * (f1 - v1);
                        }
                        uint32_t hi, lo;
                        split2(v0, v1, hi, lo);
                        Vh2[idx] = hi; Vl2[idx] = lo;
                    }
                }
            }
        }
    }
}

// ================= flash attention: Br=128, paired Qb tiles (uniform 34 tiles/CTA) =
#define ATSM_PL  2304    // uint32 per plane (64*36)
#define ATSM_BUF 9216    // uint32 per buffer (4 planes)
#define NQB (S_ / 128)   // 16 query tiles per (b,h)
__global__ void __launch_bounds__(256) attn_mma(
    const uint32_t* __restrict__ Qh, const uint32_t* __restrict__ Ql,
    const uint32_t* __restrict__ Kg_h, const uint32_t* __restrict__ Kg_l,
    const uint32_t* __restrict__ Vg_h, const uint32_t* __restrict__ Vg_l,
    uint32_t* __restrict__ Oh, uint32_t* __restrict__ Ol)
{
    extern __shared__ uint32_t asmem[];
    int h  = blockIdx.y & 7, b = blockIdx.y >> 3;
    int tid = threadIdx.x, w = tid >> 5, lane = tid & 31;
    int g = lane >> 2, t = lane & 3;

    uint32_t base = smem_u32(asmem);
    int l8 = lane & 7, seg8 = lane >> 3;

    auto load_tile = [&](int J, int buf) {
        int kr = b * S_ + J * 64;
        uint32_t bb = base + (uint32_t)buf * (ATSM_BUF * 4);
        #pragma unroll
        for (int i = 0; i < 2; i++) {
            int cc = i * 256 + tid;          // 0..511
            int row = cc >> 3, sg = cc & 7;
            size_t src = (size_t)(kr + row) * KPX + h * 32 + sg * 4;
            uint32_t soff = (uint32_t)(row * 36 + sg * 4) * 4;
            cp16(bb + soff, Kg_h + src, 16);
            cp16(bb + ATSM_PL * 4 + soff, Kg_l + src, 16);
            cp16(bb + ATSM_PL * 8 + soff, Vg_h + src, 16);
            cp16(bb + ATSM_PL * 12 + soff, Vg_l + src, 16);
        }
        asm volatile("cp.async.commit_group;" ::: "memory");
    };

    #pragma unroll 1
    for (int pass = 0; pass < 2; pass++) {
        // pair heavy+light: pass0 -> Qb = NQB-1-bx (heavy first), pass1 -> Qb = bx
        int Qb = pass == 0 ? (NQB - 1 - blockIdx.x) : blockIdx.x;
        int row0 = b * S_ + Qb * 128;

        // ---- Q fragments ----
        uint32_t qh[4][4], ql[4][4];
        #pragma unroll
        for (int kt = 0; kt < 4; kt++) {
            #pragma unroll
            for (int q = 0; q < 4; q++) {
                int rr = row0 + w * 16 + g + ((q & 1) ? 8 : 0);
                int kp = kt * 8 + t + ((q & 2) ? 4 : 0);
                size_t idx = (size_t)rr * KPX + h * 32 + kp;
                qh[kt][q] = Qh[idx];
                ql[kt][q] = Ql[idx];
            }
        }

        float Oa[8][4];
        #pragma unroll
        for (int i = 0; i < 8; i++)
            #pragma unroll
            for (int q = 0; q < 4; q++) Oa[i][q] = 0.0f;
        float m_[2] = {-INFINITY, -INFINITY};
        float l_[2] = {0.0f, 0.0f};

        int Jmax = 2 * Qb + 1;
        load_tile(0, 0);
        for (int J = 0; J <= Jmax; J++) {
            if (J < Jmax) {
                load_tile(J + 1, (J + 1) & 1);
                asm volatile("cp.async.wait_group 1;" ::: "memory");
            } else {
                asm volatile("cp.async.wait_group 0;" ::: "memory");
            }
            __syncthreads();

            uint32_t kbh = base + (uint32_t)(J & 1) * (ATSM_BUF * 4);
            uint32_t kbl = kbh + ATSM_PL * 4;
            uint32_t vbh = kbh + ATSM_PL * 8;
            uint32_t vbl = kbh + ATSM_PL * 12;

            int ntS = 8;
            if (J == 2 * Qb)       { if (w < 2) ntS = 4; }
            else if (J == Jmax)    { ntS = (w < 4) ? 0 : ((w < 6) ? 4 : 8); }

            if (ntS > 0) {
                int ktPV = ntS >> 1;

                float Sa[8][4];
                for (int nt = 0; nt < ntS; nt++) {
                    Sa[nt][0] = Sa[nt][1] = Sa[nt][2] = Sa[nt][3] = 0.0f;
                    uint32_t kfh[4][2], kfl[4][2];
                    uint32_t off0 = (uint32_t)(((8 * nt + l8) * 36 + seg8 * 4) * 4);
                    ldsm4(kfh[0][0], kfh[0][1], kfh[1][0], kfh[1][1], kbh + off0);
                    ldsm4(kfh[2][0], kfh[2][1], kfh[3][0], kfh[3][1], kbh + off0 + 64);
                    ldsm4(kfl[0][0], kfl[0][1], kfl[1][0], kfl[1][1], kbl + off0);
                    ldsm4(kfl[2][0], kfl[2][1], kfl[3][0], kfl[3][1], kbl + off0 + 64);
                    #pragma unroll
                    for (int kt = 0; kt < 4; kt++) {
                        mma16816(Sa[nt], qh[kt], kfh[kt]);
                        mma16816(Sa[nt], qh[kt], kfl[kt]);
                        mma16816(Sa[nt], ql[kt], kfh[kt]);
                    }
                }

                float alpha[2];
                #pragma unroll
                for (int half = 0; half < 2; half++) {
                    float mx = -INFINITY;
                    for (int nt = 0; nt < ntS; nt++) {
                        mx = fmaxf(mx, Sa[nt][half * 2]);
                        mx = fmaxf(mx, Sa[nt][half * 2 + 1]);
                    }
                    mx = fmaxf(mx, __shfl_xor_sync(0xffffffffu, mx, 1));
                    mx = fmaxf(mx, __shfl_xor_sync(0xffffffffu, mx, 2));
                    float mn = fmaxf(m_[half], mx);
                    alpha[half] = __expf(m_[half] - mn);
                    m_[half] = mn;
                    float ps = 0.0f;
                    for (int nt = 0; nt < ntS; nt++) {
                        float p0 = __expf(Sa[nt][half * 2]     - mn);
                        float p1 = __expf(Sa[nt][half * 2 + 1] - mn);
                        Sa[nt][half * 2]     = p0;
                        Sa[nt][half * 2 + 1] = p1;
                        ps += p0 + p1;
                    }
                    l_[half] = l_[half] * alpha[half] + ps;
                }
                #pragma unroll
                for (int nt = 0; nt < 8; nt++) {
                    Oa[nt][0] *= alpha[0]; Oa[nt][1] *= alpha[0];
                    Oa[nt][2] *= alpha[1]; Oa[nt][3] *= alpha[1];
                }

                uint32_t ph[4][4], pl[4][4];
                for (int kt = 0; kt < ktPV; kt++) {
                    split2(Sa[2 * kt][0],     Sa[2 * kt][1],     ph[kt][0], pl[kt][0]);
                    split2(Sa[2 * kt][2],     Sa[2 * kt][3],     ph[kt][1], pl[kt][1]);
                    split2(Sa[2 * kt + 1][0], Sa[2 * kt + 1][1], ph[kt][2], pl[kt][2]);
                    split2(Sa[2 * kt + 1][2], Sa[2 * kt + 1][3], ph[kt][3], pl[kt][3]);
                }

                int npair = ktPV >> 1;
                for (int p = 0; p < npair; p++) {
                    int key = 32 * p + seg8 * 8 + l8;
                    #pragma unroll
                    for (int nt = 0; nt < 8; nt++) {
                        uint32_t off = (uint32_t)((key * 36 + nt * 4) * 4);
                        uint32_t bh0, bh1, bh2, bh3, bl0, bl1, bl2, bl3;
                        ldsm4t(bh0, bh1, bh2, bh3, vbh + off);
                        ldsm4t(bl0, bl1, bl2, bl3, vbl + off);
                        uint32_t b0h[2] = {bh0, bh1}, b0l[2] = {bl0, bl1};
                        uint32_t b1h[2] = {bh2, bh3}, b1l[2] = {bl2, bl3};
                        mma16816(Oa[nt], ph[2*p],     b0h);
                        mma16816(Oa[nt], ph[2*p],     b0l);
                        mma16816(Oa[nt], pl[2*p],     b0h);
                        mma16816(Oa[nt], ph[2*p + 1], b1h);
                        mma16816(Oa[nt], ph[2*p + 1], b1l);
                        mma16816(Oa[nt], pl[2*p + 1], b1h);
                    }
                }
            }
            __syncthreads();
        }

        float linv[2];
        #pragma unroll
        for (int half = 0; half < 2; half++) {
            float l = l_[half];
            l += __shfl_xor_sync(0xffffffffu, l, 1);
            l += __shfl_xor_sync(0xffffffffu, l, 2);
            linv[half] = 1.0f / l;
        }
        int r0 = w * 16 + g, r1 = r0 + 8;
        #pragma unroll
        for (int nt = 0; nt < 8; nt++) {
            int kp = h * 32 + 4 * nt + t;
            uint32_t hi, lo;
            split2(Oa[nt][0] * linv[0], Oa[nt][1] * linv[0], hi, lo);
            Oh[(size_t)(row0 + r0) * KPX + kp] = hi;
            Ol[(size_t)(row0 + r0) * KPX + kp] = lo;
            split2(Oa[nt][2] * linv[1], Oa[nt][3] * linv[1], hi, lo);
            Oh[(size_t)(row0 + r1) * KPX + kp] = hi;
            Ol[(size_t)(row0 + r1) * KPX + kp] = lo;
        }
    }
}

// ---------------- rmsnorm -> split output ----------------
__global__ void rmsnorm_split_k(const float* __restrict__ in, const float* __restrict__ w,
                                uint32_t* __restrict__ Xh, uint32_t* __restrict__ Xl) {
    int row = blockIdx.x;
    const float4* ip = (const float4*)(in + (size_t)row * D_);
    float4 v = ip[threadIdx.x];
    float ss = v.x*v.x + v.y*v.y + v.z*v.z + v.w*v.w;
    #pragma unroll
    for (int o = 16; o; o >>= 1) ss += __shfl_xor_sync(0xffffffffu, ss, o);
    __shared__ float sred[4];
    if ((threadIdx.x & 31) == 0) sred[threadIdx.x >> 5] = ss;
    __syncthreads();
    float tot = sred[0] + sred[1] + sred[2] + sred[3];
    float sc = rsqrtf(tot * (1.0f / 512.0f) + 1.1920929e-7f);
    const float4* wp = (const float4*)w;
    float4 wv = wp[threadIdx.x];
    float o0 = v.x * sc * wv.x, o1 = v.y * sc * wv.y;
    float o2 = v.z * sc * wv.z, o3 = v.w * sc * wv.w;
    uint32_t h0, l0, h1, l1;
    split2(o0, o1, h0, l0);
    split2(o2, o3, h1, l1);
    size_t base = (size_t)row * KPX + threadIdx.x * 2;
    Xh[base] = h0; Xh[base + 1] = h1;
    Xl[base] = l0; Xl[base + 1] = l1;
}

// ---------------- mix gate ----------------
__global__ void mix_k(const uint32_t* __restrict__ Xh, const uint32_t* __restrict__ Xl,
                      const float* __restrict__ mw, const float* __restrict__ mb,
                      float* __restrict__ mix) {
    int row = blockIdx.x;
    int lane = threadIdx.x & 31;
    int h = threadIdx.x >> 5;
    float dot = 0.0f;
    #pragma unroll
    for (int kp = lane; kp < KPX; kp += 32) {
        uint32_t hv = Xh[(size_t)row * KPX + kp], lv = Xl[(size_t)row * KPX + kp];
        float x0 = __uint_as_float(hv << 16) + __uint_as_float(lv << 16);
        float x1 = __uint_as_float(hv & 0xFFFF0000u) + __uint_as_float(lv & 0xFFFF0000u);
        dot += x0 * mw[(2 * kp) * H_ + h] + x1 * mw[(2 * kp + 1) * H_ + h];
    }
    #pragma unroll
    for (int o = 16; o; o >>= 1) dot += __shfl_xor_sync(0xffffffffu, dot, o);
    if (lane == 0)
        mix[(size_t)row * H_ + h] = 1.0f / (1.0f + expf(-(dot + mb[h])));
}

// ---------------- rmsnorm fp32 out (final) ----------------
__global__ void rmsnorm_k(const float* __restrict__ in, const float* __restrict__ w,
                          float* __restrict__ out) {
    int row = blockIdx.x;
    const float4* ip = (const float4*)(in + (size_t)row * D_);
    float4 v = ip[threadIdx.x];
    float ss = v.x*v.x + v.y*v.y + v.z*v.z + v.w*v.w;
    #pragma unroll
    for (int o = 16; o; o >>= 1) ss += __shfl_xor_sync(0xffffffffu, ss, o);
    __shared__ float sred[4];
    if ((threadIdx.x & 31) == 0) sred[threadIdx.x >> 5] = ss;
    __syncthreads();
    float tot = sred[0] + sred[1] + sred[2] + sred[3];
    float sc = rsqrtf(tot * (1.0f / 512.0f) + 1.1920929e-7f);
    const float4* wp = (const float4*)w;
    float4 wv = wp[threadIdx.x];
    float4 o4;
    o4.x = v.x * sc * wv.x; o4.y = v.y * sc * wv.y;
    o4.z = v.z * sc * wv.z; o4.w = v.w * sc * wv.w;
    ((float4*)(out + (size_t)row * D_))[threadIdx.x] = o4;
}

// ---------------- launch ----------------
extern "C" void kernel_launch(void* const* d_in, const int* in_sizes, int n_in,
                              void* d_out, int out_size) {
    const float* tokens       = (const float*)d_in[0];
    const float* attn_norm_w  = (const float*)d_in[1];
    const float* qkv_w        = (const float*)d_in[2];
    const float* out_w        = (const float*)d_in[3];
    const float* mix_w        = (const float*)d_in[4];
    const float* mix_b        = (const float*)d_in[5];
    const float* ff_norm_w    = (const float*)d_in[6];
    const float* ff_in_w      = (const float*)d_in[7];
    const float* ff_in_b      = (const float*)d_in[8];
    const float* ff_out_w     = (const float*)d_in[9];
    const float* ff_out_b     = (const float*)d_in[10];
    const float* final_norm_w = (const float*)d_in[11];

    float *t_, *fv_, *mix_;
    float2* rt_;
    uint32_t *xh_, *xl_, *oh_, *ol_, *yh_, *yl_;
    uint32_t *qh2_, *ql2_, *kh2_, *kl2_, *vh2_, *vl2_;
    uint32_t *wqh_, *wql_, *woh_, *wol_, *wfh_, *wfl_, *wgh_, *wgl_;
    cudaGetSymbolAddress((void**)&t_,   g_t);
    cudaGetSymbolAddress((void**)&fv_,  g_fv);
    cudaGetSymbolAddress((void**)&mix_, g_mix);
    cudaGetSymbolAddress((void**)&rt_,  g_rt);
    cudaGetSymbolAddress((void**)&xh_,  g_xh);
    cudaGetSymbolAddress((void**)&xl_,  g_xl);
    cudaGetSymbolAddress((void**)&oh_,  g_oh);
    cudaGetSymbolAddress((void**)&ol_,  g_ol);
    cudaGetSymbolAddress((void**)&yh_,  g_yh);
    cudaGetSymbolAddress((void**)&yl_,  g_yl);
    cudaGetSymbolAddress((void**)&qh2_, g_qh2);
    cudaGetSymbolAddress((void**)&ql2_, g_ql2);
    cudaGetSymbolAddress((void**)&kh2_, g_kh2);
    cudaGetSymbolAddress((void**)&kl2_, g_kl2);
    cudaGetSymbolAddress((void**)&vh2_, g_vh2);
    cudaGetSymbolAddress((void**)&vl2_, g_vl2);
    cudaGetSymbolAddress((void**)&wqh_, g_wqh);
    cudaGetSymbolAddress((void**)&wql_, g_wql);
    cudaGetSymbolAddress((void**)&woh_, g_woh);
    cudaGetSymbolAddress((void**)&wol_, g_wol);
    cudaGetSymbolAddress((void**)&wfh_, g_wfh);
    cudaGetSymbolAddress((void**)&wfl_, g_wfl);
    cudaGetSymbolAddress((void**)&wgh_, g_wgh);
    cudaGetSymbolAddress((void**)&wgl_, g_wgl);

    const int GSM4 = 2 * (2 * 128 * 20 + 2 * BPL) * 4;   // 81920
    const int GSM2 = 2 * (2 * 64 * 20 + 2 * BPL) * 4;    // 61440
    const int ASM  = 2 * ATSM_BUF * 4;
    static int smem_set = 0;
    if (!smem_set) {
        cudaFuncSetAttribute(gemm_bs<4>, cudaFuncAttributeMaxDynamicSharedMemorySize, GSM4);
        cudaFuncSetAttribute(gemm_bs<2>, cudaFuncAttributeMaxDynamicSharedMemorySize, GSM2);
        cudaFuncSetAttribute(attn_mma, cudaFuncAttributeMaxDynamicSharedMemorySize, ASM);
        smem_set = 1;
    }

    ropetab_k<<<(S_ * 32 + 255) / 256, 256>>>(rt_);

    dim3 cb(32, 8);
    wconv_k<<<dim3(KPX / 32, QKVN / 32, L_), cb>>>(
        qkv_w, wqh_, wql_, D_, QKVN, KPX, 0,
        (size_t)D_ * QKVN, (size_t)QKVN * KPX);
    wconv_k<<<dim3(KPX / 32, DI / 32, L_), cb>>>(
        out_w, woh_, wol_, DI, D_, KPX, 0,
        (size_t)DI * D_, (size_t)DI * KPX);
    wconv_k<<<dim3(KPX / 32, (FFN + 31) / 32, L_), cb>>>(
        ff_in_w, wfh_, wfl_, D_, FFN, KPX, 1,
        (size_t)D_ * FFN, (size_t)FFN * KPX);
    wconv_k<<<dim3((KPY + 31) / 32, DI / 32, L_), cb>>>(
        ff_out_w, wgh_, wgl_, DHID, D_, KPY, 0,
        (size_t)DHID * D_, (size_t)DI * KPY);

    for (int l = 0; l < L_; l++) {
        const float* res_in = (l == 0) ? tokens : t_;

        rmsnorm_split_k<<<M_, 128>>>(res_in, attn_norm_w + l * D_, xh_, xl_);

        if (l > 0)
            mix_k<<<M_, 256>>>(xh_, xl_, mix_w + (size_t)l * D_ * H_, mix_b + l * H_, mix_);

        gemm_bs<4><<<dim3(QKVN / 128, M_ / 128), 256, GSM4>>>(
            QKVN, KPX, KPX, KPX, 0,
            xh_, xl_, wqh_ + (size_t)l * QKVN * KPX, wql_ + (size_t)l * QKVN * KPX,
            nullptr, nullptr, nullptr, 2, nullptr, nullptr,
            rt_, mix_, fv_, qh2_, ql2_, kh2_, kl2_, vh2_, vl2_, (l == 0) ? 1 : 0);

        attn_mma<<<dim3(NQB / 2, B_ * H_), 256, ASM>>>(
            qh2_, ql2_, kh2_, kl2_, vh2_, vl2_, oh_, ol_);

        gemm_bs<2><<<dim3(D_ / 128, M_ / 64), 256, GSM2>>>(
            D_, KPX, KPX, KPX, D_,
            oh_, ol_, woh_ + (size_t)l * DI * KPX, wol_ + (size_t)l * DI * KPX,
            t_, nullptr, res_in, 0, nullptr, nullptr,
            nullptr, nullptr, nullptr, nullptr, nullptr, nullptr, nullptr, nullptr, nullptr, 0);

        rmsnorm_split_k<<<M_, 128>>>(t_, ff_norm_w + l * D_, xh_, xl_);

        gemm_bs<4><<<dim3((FFN + 127) / 128, M_ / 128), 256, GSM4>>>(
            FFN, KPX, KPX, KPX, 0,
            xh_, xl_, wfh_ + (size_t)l * FFN * KPX, wfl_ + (size_t)l * FFN * KPX,
            nullptr, ff_in_b + (size_t)l * FFN, nullptr, 1, yh_, yl_,
            nullptr, nullptr, nullptr, nullptr, nullptr, nullptr, nullptr, nullptr, nullptr, 0);

        gemm_bs<2><<<dim3(D_ / 128, M_ / 64), 256, GSM2>>>(
            D_, KPY, KPY, KPY, D_,
            yh_, yl_, wgh_ + (size_t)l * DI * KPY, wgl_ + (size_t)l * DI * KPY,
            t_, ff_out_b + (size_t)l * D_, t_, 0, nullptr, nullptr,
            nullptr, nullptr, nullptr, nullptr, nullptr, nullptr, nullptr, nullptr, nullptr, 0);
    }

    rmsnorm_k<<<M_, 128>>>(t_, final_norm_w, (float*)d_out);
}